// round 9
// baseline (speedup 1.0000x reference)
#include <cuda_runtime.h>
#include <cuda_fp16.h>

#define NMAX 100000
#define EMAX 1600000
#define HID 128
#define EPS 1e-5f
#define CHUNK 1024
#define NBLK ((NMAX + CHUNK - 1) / CHUNK)   // 98

// Scratch (no cudaMalloc allowed).
__device__ float4 g_h0  [(size_t)NMAX * HID / 4];  // post-linear ("ori"), fp32
__device__ uint4  g_act [(size_t)NMAX * HID / 8];  // layer-0 input, fp16 (8 halfs/uint4)
__device__ uint4  g_act2[(size_t)NMAX * HID / 8];  // layer-1 input, fp16
__device__ int2   g_srcw[EMAX];                    // CSR payload: (src, w-bits)
__device__ int    g_off [NMAX + 1];
__device__ int    g_cur [NMAX];
__device__ int    g_deg [NMAX];
__device__ int    g_bsum[NBLK + 1];

__device__ __forceinline__ unsigned pack_h2(float a, float b)
{
    half2 h = __floats2half2_rn(a, b);
    return *(unsigned*)&h;
}

// ---------------------------------------------------------------------------
// GEMM + bias + fused LN0 + ReLU.  64 rows/block, 512 threads (16 warps x 4
// rows).  Trailing blocks zero the degree array.
// ---------------------------------------------------------------------------
extern __shared__ float smem_dyn[];
__global__ void gemm_ln_kernel(const float* __restrict__ x,
                               const float* __restrict__ W,
                               const float* __restrict__ b,
                               const float* __restrict__ lns,
                               const float* __restrict__ lnb,
                               float* __restrict__ h0,
                               unsigned* __restrict__ act,   // fp16 x2 per word
                               int* __restrict__ deg,
                               int n, int gemm_blocks)
{
    if (blockIdx.x >= gemm_blocks) {
        int zb = blockIdx.x - gemm_blocks;
        int i = zb * CHUNK + threadIdx.x;
        if (i < n) deg[i] = 0;
        i += 512;
        if (i < n) deg[i] = 0;
        return;
    }

    float4* Ws4 = (float4*)smem_dyn;            // [128][33] float4 (stride 132 f)
    float*  xs  = smem_dyn + 128 * 132;         // 64 rows * 128
    const int tid  = threadIdx.x;
    const int lane = tid & 31;
    const int warp = tid >> 5;                  // 0..15
    const int row0 = blockIdx.x * 64;

    for (int idx = tid; idx < HID * HID; idx += 512) {
        int j = idx >> 7, k = idx & 127;
        smem_dyn[k * 132 + j] = W[idx];
    }
    for (int idx = tid; idx < 64 * HID; idx += 512) {
        int r = idx >> 7, k = idx & 127;
        int row = row0 + r;
        xs[r * HID + k] = (row < n) ? x[(size_t)row * HID + k] : 0.f;
    }
    __syncthreads();

    const int r0 = warp * 4;
    float acc[4][4];
    #pragma unroll
    for (int i = 0; i < 4; i++)
        #pragma unroll
        for (int c = 0; c < 4; c++) acc[i][c] = 0.f;

    #pragma unroll 2
    for (int k0 = 0; k0 < HID; k0 += 4) {
        float4 w0 = Ws4[(k0 + 0) * 33 + lane];
        float4 w1 = Ws4[(k0 + 1) * 33 + lane];
        float4 w2 = Ws4[(k0 + 2) * 33 + lane];
        float4 w3 = Ws4[(k0 + 3) * 33 + lane];
        #pragma unroll
        for (int i = 0; i < 4; i++) {
            float4 xv = *(const float4*)&xs[(r0 + i) * HID + k0];
            acc[i][0] += xv.x * w0.x; acc[i][0] += xv.y * w1.x;
            acc[i][0] += xv.z * w2.x; acc[i][0] += xv.w * w3.x;
            acc[i][1] += xv.x * w0.y; acc[i][1] += xv.y * w1.y;
            acc[i][1] += xv.z * w2.y; acc[i][1] += xv.w * w3.y;
            acc[i][2] += xv.x * w0.z; acc[i][2] += xv.y * w1.z;
            acc[i][2] += xv.z * w2.z; acc[i][2] += xv.w * w3.z;
            acc[i][3] += xv.x * w0.w; acc[i][3] += xv.y * w1.w;
            acc[i][3] += xv.z * w2.w; acc[i][3] += xv.w * w3.w;
        }
    }

    const int j0 = lane * 4;
    float4 bv = *(const float4*)&b[j0];
    float4 sc = *(const float4*)&lns[j0];
    float4 bi = *(const float4*)&lnb[j0];

    #pragma unroll
    for (int i = 0; i < 4; i++) {
        int row = row0 + r0 + i;
        if (row < n) {
            float4 h;
            h.x = acc[i][0] + bv.x; h.y = acc[i][1] + bv.y;
            h.z = acc[i][2] + bv.z; h.w = acc[i][3] + bv.w;
            *(float4*)&h0[(size_t)row * HID + j0] = h;

            float s = h.x + h.y + h.z + h.w;
            #pragma unroll
            for (int o = 16; o > 0; o >>= 1) s += __shfl_xor_sync(0xffffffffu, s, o);
            float mu = s * (1.f / HID);
            float dx = h.x - mu, dy = h.y - mu, dz = h.z - mu, dw = h.w - mu;
            float q = dx * dx + dy * dy + dz * dz + dw * dw;
            #pragma unroll
            for (int o = 16; o > 0; o >>= 1) q += __shfl_xor_sync(0xffffffffu, q, o);
            float rstd = rsqrtf(q * (1.f / HID) + EPS);

            // 2 halfs per 32-bit word, 2 words per lane (cols j0..j0+3)
            unsigned lo = pack_h2(fmaxf(dx * rstd * sc.x + bi.x, 0.f),
                                  fmaxf(dy * rstd * sc.y + bi.y, 0.f));
            unsigned hi = pack_h2(fmaxf(dz * rstd * sc.z + bi.z, 0.f),
                                  fmaxf(dw * rstd * sc.w + bi.w, 0.f));
            uint2* dstp = (uint2*)&act[(size_t)row * 64 + lane * 2];
            *dstp = make_uint2(lo, hi);
        }
    }
}

// ---------------------------------------------------------------------------
// CSR build
// ---------------------------------------------------------------------------
__global__ void hist_kernel(const int* __restrict__ dst, int* __restrict__ deg, int E)
{
    int e0 = (blockIdx.x * blockDim.x + threadIdx.x) * 4;
    if (e0 + 3 < E) {
        int4 d = *(const int4*)&dst[e0];
        atomicAdd(&deg[d.x], 1); atomicAdd(&deg[d.y], 1);
        atomicAdd(&deg[d.z], 1); atomicAdd(&deg[d.w], 1);
    } else {
        for (int e = e0; e < E; e++) atomicAdd(&deg[dst[e]], 1);
    }
}

__global__ void reduce_kernel(const int* __restrict__ deg,
                              int* __restrict__ bsum, int n)
{
    __shared__ int sh[256];
    const int t = threadIdx.x;
    const int base = blockIdx.x * CHUNK;
    int s = 0;
    #pragma unroll
    for (int j = 0; j < CHUNK / 256; j++) {
        int i = base + j * 256 + t;
        if (i < n) s += deg[i];
    }
    sh[t] = s;
    __syncthreads();
    #pragma unroll
    for (int o = 128; o > 0; o >>= 1) {
        if (t < o) sh[t] += sh[t + o];
        __syncthreads();
    }
    if (t == 0) bsum[blockIdx.x] = sh[0];
}

__global__ void scan_bsum_kernel(int* __restrict__ bsum, int nb)
{
    __shared__ int sh[128];
    const int t = threadIdx.x;
    int v = (t < nb) ? bsum[t] : 0;
    sh[t] = v;
    __syncthreads();
    for (int o = 1; o < 128; o <<= 1) {
        int u = (t >= o) ? sh[t - o] : 0;
        __syncthreads();
        sh[t] += u;
        __syncthreads();
    }
    if (t < nb) bsum[t] = sh[t] - v;        // exclusive
    if (t == nb - 1) bsum[nb] = sh[t];      // total
}

__global__ void write_off_kernel(const int* __restrict__ deg,
                                 const int* __restrict__ bsum,
                                 int* __restrict__ off,
                                 int* __restrict__ cur, int n, int nb)
{
    __shared__ int sh[256];
    const int t = threadIdx.x;
    const int base = blockIdx.x * CHUNK + t * 4;

    int d[4];
    #pragma unroll
    for (int j = 0; j < 4; j++)
        d[j] = (base + j < n) ? deg[base + j] : 0;

    int local = d[0] + d[1] + d[2] + d[3];
    sh[t] = local;
    __syncthreads();
    for (int o = 1; o < 256; o <<= 1) {
        int u = (t >= o) ? sh[t - o] : 0;
        __syncthreads();
        sh[t] += u;
        __syncthreads();
    }
    int run = bsum[blockIdx.x] + sh[t] - local;
    #pragma unroll
    for (int j = 0; j < 4; j++) {
        int i = base + j;
        if (i < n) { off[i] = run; cur[i] = run; run += d[j]; }
    }
    if (blockIdx.x == 0 && t == 0) off[n] = bsum[nb];
}

__global__ void fill_kernel(const int* __restrict__ src, const int* __restrict__ dst,
                            const float* __restrict__ ef,
                            int* __restrict__ cur, int2* __restrict__ srcw, int E)
{
    int e0 = (blockIdx.x * blockDim.x + threadIdx.x) * 4;
    if (e0 + 3 < E) {
        int4   s = *(const int4*)&src[e0];
        int4   d = *(const int4*)&dst[e0];
        float4 w = *(const float4*)&ef[e0];
        int p0 = atomicAdd(&cur[d.x], 1);
        int p1 = atomicAdd(&cur[d.y], 1);
        int p2 = atomicAdd(&cur[d.z], 1);
        int p3 = atomicAdd(&cur[d.w], 1);
        srcw[p0] = make_int2(s.x, __float_as_int(w.x));
        srcw[p1] = make_int2(s.y, __float_as_int(w.y));
        srcw[p2] = make_int2(s.z, __float_as_int(w.z));
        srcw[p3] = make_int2(s.w, __float_as_int(w.w));
    } else {
        for (int e = e0; e < E; e++) {
            int p = atomicAdd(&cur[dst[e]], 1);
            srcw[p] = make_int2(src[e], __float_as_int(ef[e]));
        }
    }
}

// ---------------------------------------------------------------------------
// SpMM gather-reduce over fp16 features: warp per node, TWO edges per
// iteration.  Half-warp h (lanes 16h..16h+15) gathers edge j+h with one
// LDG.128 (16 lanes x 16B = full 256B row).  Each lane accumulates 8 columns
// [halfLane*8, halfLane*8+8) in fp32; a final shfl_xor(16) folds the two
// half-warp partial sums (both halves end up with identical values).
// ---------------------------------------------------------------------------
template <bool FUSE_LN>
__global__ void spmm_csr_kernel(const int* __restrict__ off,
                                const int2* __restrict__ srcw,
                                const uint4* __restrict__ hin,   // 16 uint4 / row
                                const float4* __restrict__ h0,
                                const float* __restrict__ lns,
                                const float* __restrict__ lnb,
                                uint4* __restrict__ out_h,       // 16 uint4 / row
                                float4* __restrict__ out_f, int n)
{
    const int node = blockIdx.x * 8 + (threadIdx.x >> 5);
    const int lane = threadIdx.x & 31;
    const int hl   = lane & 15;        // position within half-warp
    const int pair = lane >> 4;        // 0 or 1: which edge of the pair
    if (node >= n) return;

    const int beg = off[node];
    const int end = off[node + 1];

    float a[8];
    #pragma unroll
    for (int k = 0; k < 8; k++) a[k] = 0.f;

    for (int base = beg; base < end; base += 32) {
        int cnt = min(end - base, 32);
        int2 sw = make_int2(0, 0);               // w=0 for idle lanes
        if (lane < cnt) sw = __ldg(&srcw[base + lane]);
        #pragma unroll 8
        for (int j = 0; j < cnt; j += 2) {
            int jj = j + pair;                   // may be == cnt (odd): w=0,s=0
            int   s = __shfl_sync(0xffffffffu, sw.x, jj);
            float w = __int_as_float(__shfl_sync(0xffffffffu, sw.y, jj));
            uint4 p = __ldg(&hin[(size_t)s * 16 + hl]);
            float2 f0 = __half22float2(*(half2*)&p.x);
            float2 f1 = __half22float2(*(half2*)&p.y);
            float2 f2 = __half22float2(*(half2*)&p.z);
            float2 f3 = __half22float2(*(half2*)&p.w);
            a[0] += f0.x * w; a[1] += f0.y * w;
            a[2] += f1.x * w; a[3] += f1.y * w;
            a[4] += f2.x * w; a[5] += f2.y * w;
            a[6] += f3.x * w; a[7] += f3.y * w;
        }
    }

    // Fold the two half-warp partials; both halves now hold identical sums.
    #pragma unroll
    for (int k = 0; k < 8; k++)
        a[k] += __shfl_xor_sync(0xffffffffu, a[k], 16);

    if (FUSE_LN) {
        // Residual (cols hl*8 .. hl*8+7); loaded by all lanes (halves identical)
        float4 r0 = __ldg(&h0[(size_t)node * 32 + hl * 2 + 0]);
        float4 r1 = __ldg(&h0[(size_t)node * 32 + hl * 2 + 1]);
        a[0] += r0.x; a[1] += r0.y; a[2] += r0.z; a[3] += r0.w;
        a[4] += r1.x; a[5] += r1.y; a[6] += r1.z; a[7] += r1.w;

        float s = 0.f, q;
        #pragma unroll
        for (int k = 0; k < 8; k++) s += a[k];
        #pragma unroll
        for (int o = 16; o > 0; o >>= 1) s += __shfl_xor_sync(0xffffffffu, s, o);
        float mu = s * (1.f / (2 * HID));        // each col counted twice
        q = 0.f;
        #pragma unroll
        for (int k = 0; k < 8; k++) { a[k] -= mu; q += a[k] * a[k]; }
        #pragma unroll
        for (int o = 16; o > 0; o >>= 1) q += __shfl_xor_sync(0xffffffffu, q, o);
        float rstd = rsqrtf(q * (1.f / (2 * HID)) + EPS);

        if (pair == 0) {
            int j0 = hl * 8;
            float4 sc0 = __ldg((const float4*)&lns[j0]);
            float4 sc1 = __ldg((const float4*)&lns[j0 + 4]);
            float4 bi0 = __ldg((const float4*)&lnb[j0]);
            float4 bi1 = __ldg((const float4*)&lnb[j0 + 4]);
            uint4 o4;
            o4.x = pack_h2(fmaxf(a[0] * rstd * sc0.x + bi0.x, 0.f),
                           fmaxf(a[1] * rstd * sc0.y + bi0.y, 0.f));
            o4.y = pack_h2(fmaxf(a[2] * rstd * sc0.z + bi0.z, 0.f),
                           fmaxf(a[3] * rstd * sc0.w + bi0.w, 0.f));
            o4.z = pack_h2(fmaxf(a[4] * rstd * sc1.x + bi1.x, 0.f),
                           fmaxf(a[5] * rstd * sc1.y + bi1.y, 0.f));
            o4.w = pack_h2(fmaxf(a[6] * rstd * sc1.z + bi1.z, 0.f),
                           fmaxf(a[7] * rstd * sc1.w + bi1.w, 0.f));
            out_h[(size_t)node * 16 + hl] = o4;
        }
    } else {
        if (pair == 0) {
            float4 o0 = make_float4(a[0], a[1], a[2], a[3]);
            float4 o1 = make_float4(a[4], a[5], a[6], a[7]);
            out_f[(size_t)node * 32 + hl * 2 + 0] = o0;
            out_f[(size_t)node * 32 + hl * 2 + 1] = o1;
        }
    }
}

// ---------------------------------------------------------------------------
extern "C" void kernel_launch(void* const* d_in, const int* in_sizes, int n_in,
                              void* d_out, int out_size)
{
    const float* x   = (const float*)d_in[0];
    const int*   ei  = (const int*)d_in[1];     // [2, E] int32
    const float* ef  = (const float*)d_in[2];
    const float* W   = (const float*)d_in[3];
    const float* b   = (const float*)d_in[4];
    const float* lns = (const float*)d_in[5];
    const float* lnb = (const float*)d_in[6];

    const int n = in_sizes[0] / HID;
    const int E = in_sizes[2];
    float4* out = (float4*)d_out;

    float4 *h0; uint4 *act, *act2; int2* srcw; int *off, *cur, *deg, *bsum;
    cudaGetSymbolAddress((void**)&h0,   g_h0);
    cudaGetSymbolAddress((void**)&act,  g_act);
    cudaGetSymbolAddress((void**)&act2, g_act2);
    cudaGetSymbolAddress((void**)&srcw, g_srcw);
    cudaGetSymbolAddress((void**)&off,  g_off);
    cudaGetSymbolAddress((void**)&cur,  g_cur);
    cudaGetSymbolAddress((void**)&deg,  g_deg);
    cudaGetSymbolAddress((void**)&bsum, g_bsum);

    const int nb = (n + CHUNK - 1) / CHUNK;

    // 1. Linear + LN0 + ReLU (fused) with fused deg-zeroing blocks
    const int gemm_blocks = (n + 63) / 64;
    const int gemm_smem = (128 * 132 + 64 * HID) * (int)sizeof(float); // 100352 B
    cudaFuncSetAttribute(gemm_ln_kernel,
                         cudaFuncAttributeMaxDynamicSharedMemorySize, gemm_smem);
    gemm_ln_kernel<<<gemm_blocks + nb, 512, gemm_smem>>>(x, W, b, lns, lnb,
                                                         (float*)h0,
                                                         (unsigned*)act, deg,
                                                         n, gemm_blocks);

    // 2. CSR build (dst-grouped)
    hist_kernel<<<(E / 4 + 255) / 256, 256>>>(ei + E, deg, E);
    reduce_kernel<<<nb, 256>>>(deg, bsum, n);
    scan_bsum_kernel<<<1, 128>>>(bsum, nb);
    write_off_kernel<<<nb, 256>>>(deg, bsum, off, cur, n, nb);
    fill_kernel<<<(E / 4 + 255) / 256, 256>>>(ei, ei + E, ef, cur, srcw, E);

    // 3. Layer 0 aggregation + residual + LN1 + ReLU (fused), act2 in fp16
    const int spmm_blocks = (n + 7) / 8;
    spmm_csr_kernel<true><<<spmm_blocks, 256>>>(off, srcw, act, h0,
                                                lns + HID, lnb + HID,
                                                act2, nullptr, n);

    // 4. Layer 1 aggregation -> final fp32 output
    spmm_csr_kernel<false><<<spmm_blocks, 256>>>(off, srcw, act2, nullptr,
                                                 nullptr, nullptr,
                                                 nullptr, out, n);
}

// round 12
// speedup vs baseline: 1.2078x; 1.2078x over previous
#include <cuda_runtime.h>
#include <cuda_fp16.h>
#include <cstdint>

#define NMAX 100000
#define EMAX 1600000
#define HID 128
#define EPS 1e-5f
#define CHUNK 1024
#define NBLK ((NMAX + CHUNK - 1) / CHUNK)   // 98
#define GLDA 136    // smem row stride in halfs: 272B = 17 x 16B -> ldmatrix conflict-free

// Scratch (no cudaMalloc allowed).
__device__ float4 g_h0  [(size_t)NMAX * HID / 4];  // post-linear ("ori"), fp32
__device__ uint2  g_act [(size_t)NMAX * HID / 4];  // layer-0 input, fp16
__device__ uint2  g_act2[(size_t)NMAX * HID / 4];  // layer-1 input, fp16
__device__ int2   g_srcw[EMAX];                    // CSR payload: (src, w-bits)
__device__ int    g_off [NMAX + 1];
__device__ int    g_cur [NMAX];
__device__ int    g_deg [NMAX];
__device__ int    g_bsum[NBLK + 1];

__device__ __forceinline__ unsigned pack_h2(float a, float b)
{
    half2 h = __floats2half2_rn(a, b);
    return *(unsigned*)&h;
}

__device__ __forceinline__ uint2 pack_h4(float a, float b, float c, float d)
{
    return make_uint2(pack_h2(a, b), pack_h2(c, d));
}

__device__ __forceinline__ uint32_t s2u(const void* p)
{
    uint32_t a;
    asm("{ .reg .u64 t; cvta.to.shared.u64 t, %1; cvt.u32.u64 %0, t; }"
        : "=r"(a) : "l"(p));
    return a;
}

__device__ __forceinline__ void ldm_x4(uint32_t* r, uint32_t addr)
{
    asm volatile("ldmatrix.sync.aligned.m8n8.x4.shared.b16 {%0,%1,%2,%3}, [%4];"
                 : "=r"(r[0]), "=r"(r[1]), "=r"(r[2]), "=r"(r[3]) : "r"(addr));
}

__device__ __forceinline__ void ldm_x2(uint32_t* r, uint32_t addr)
{
    asm volatile("ldmatrix.sync.aligned.m8n8.x2.shared.b16 {%0,%1}, [%2];"
                 : "=r"(r[0]), "=r"(r[1]) : "r"(addr));
}

__device__ __forceinline__ void mma16816(float* c, const uint32_t* a, const uint32_t* b)
{
    asm volatile("mma.sync.aligned.m16n8k16.row.col.f32.f16.f16.f32 "
                 "{%0,%1,%2,%3}, {%4,%5,%6,%7}, {%8,%9}, {%0,%1,%2,%3};"
                 : "+f"(c[0]), "+f"(c[1]), "+f"(c[2]), "+f"(c[3])
                 : "r"(a[0]), "r"(a[1]), "r"(a[2]), "r"(a[3]),
                   "r"(b[0]), "r"(b[1]));
}

// ---------------------------------------------------------------------------
// Tensor-core GEMM (fp16 in, fp32 accum) + bias + fused LN0 + ReLU epilogue.
// Block = 256 threads / 8 warps; block tile 128 rows x 128 cols; warp = 16
// rows x 128 cols (16 m16n8 C-frags, K-loop of 8 x k16).  Trailing blocks
// zero the degree array.  Writes h0 (fp32, pre-LN) and act (fp16 post-LN+ReLU).
// ---------------------------------------------------------------------------
extern __shared__ char smem_raw[];
__global__ void gemm_ln_kernel(const float* __restrict__ x,
                               const float* __restrict__ W,
                               const float* __restrict__ b,
                               const float* __restrict__ lns,
                               const float* __restrict__ lnb,
                               float* __restrict__ h0,
                               unsigned* __restrict__ act,
                               int* __restrict__ deg,
                               int n, int gemm_blocks)
{
    if (blockIdx.x >= gemm_blocks) {          // fused deg-zeroing blocks
        int zb = blockIdx.x - gemm_blocks;
        #pragma unroll
        for (int j = 0; j < 4; j++) {
            int i = zb * CHUNK + j * 256 + threadIdx.x;
            if (i < n) deg[i] = 0;
        }
        return;
    }

    half* ws = (half*)smem_raw;               // [128][GLDA] fp16 W
    half* xs = ws + 128 * GLDA;               // [128][GLDA] fp16 x tile
    const int tid  = threadIdx.x;
    const int lane = tid & 31;
    const int warp = tid >> 5;                // 0..7
    const int row0 = blockIdx.x * 128;

    // Stage W (fp32 -> fp16): ws[j][k] = W[j*128+k]  (B operand: n-major, k-contig)
    for (int idx = tid; idx < HID * HID; idx += 256) {
        int j = idx >> 7, k = idx & 127;
        ws[j * GLDA + k] = __float2half(W[idx]);
    }
    // Stage x tile (fp32 -> fp16), zero-pad beyond n
    for (int idx = tid; idx < 128 * HID; idx += 256) {
        int r = idx >> 7, k = idx & 127;
        int row = row0 + r;
        xs[r * GLDA + k] = (row < n) ? __float2half(x[(size_t)row * HID + k])
                                     : __half(0.f);
    }
    __syncthreads();

    const uint32_t xs_u = s2u(xs);
    const uint32_t ws_u = s2u(ws);

    float c[16][4];
    #pragma unroll
    for (int t = 0; t < 16; t++)
        #pragma unroll
        for (int i = 0; i < 4; i++) c[t][i] = 0.f;

    // A-frag address: row = warp*16 + (lane&15), col = k + ((lane>>4)<<3)
    const uint32_t a_base = xs_u +
        (uint32_t)(((warp * 16 + (lane & 15)) * GLDA + ((lane >> 4) << 3)) * 2);
    // B-frag (x2): row(n) = t*8 + (lane&7), col = k + (((lane>>3)&1)<<3)
    const uint32_t b_base = ws_u +
        (uint32_t)((((lane & 7)) * GLDA + (((lane >> 3) & 1) << 3)) * 2);

    #pragma unroll
    for (int ks = 0; ks < 8; ks++) {
        const uint32_t koff = ks * 16 * 2;    // bytes
        uint32_t a[4];
        ldm_x4(a, a_base + koff);
        #pragma unroll
        for (int t = 0; t < 16; t++) {
            uint32_t bf[2];
            ldm_x2(bf, b_base + (uint32_t)(t * 8 * GLDA * 2) + koff);
            mma16816(c[t], a, bf);
        }
    }

    // Add bias into C (cols for tile t: t*8 + (lane%4)*2, +1; same for both rows)
    #pragma unroll
    for (int t = 0; t < 16; t++) {
        float2 bb = __ldg((const float2*)&b[t * 8 + (lane & 3) * 2]);
        c[t][0] += bb.x; c[t][1] += bb.y;
        c[t][2] += bb.x; c[t][3] += bb.y;
    }

    const int row_lo = row0 + warp * 16 + (lane >> 2);
    const int row_hi = row_lo + 8;

    // LN pass 1: row sums (quad reduction over lanes sharing lane>>2)
    float s_lo = 0.f, s_hi = 0.f;
    #pragma unroll
    for (int t = 0; t < 16; t++) {
        s_lo += c[t][0] + c[t][1];
        s_hi += c[t][2] + c[t][3];
    }
    s_lo += __shfl_xor_sync(0xffffffffu, s_lo, 1);
    s_lo += __shfl_xor_sync(0xffffffffu, s_lo, 2);
    s_hi += __shfl_xor_sync(0xffffffffu, s_hi, 1);
    s_hi += __shfl_xor_sync(0xffffffffu, s_hi, 2);
    const float mu_lo = s_lo * (1.f / HID);
    const float mu_hi = s_hi * (1.f / HID);

    // LN pass 2: variance
    float q_lo = 0.f, q_hi = 0.f;
    #pragma unroll
    for (int t = 0; t < 16; t++) {
        float d0 = c[t][0] - mu_lo, d1 = c[t][1] - mu_lo;
        float d2 = c[t][2] - mu_hi, d3 = c[t][3] - mu_hi;
        q_lo += d0 * d0 + d1 * d1;
        q_hi += d2 * d2 + d3 * d3;
    }
    q_lo += __shfl_xor_sync(0xffffffffu, q_lo, 1);
    q_lo += __shfl_xor_sync(0xffffffffu, q_lo, 2);
    q_hi += __shfl_xor_sync(0xffffffffu, q_hi, 1);
    q_hi += __shfl_xor_sync(0xffffffffu, q_hi, 2);
    const float rstd_lo = rsqrtf(q_lo * (1.f / HID) + EPS);
    const float rstd_hi = rsqrtf(q_hi * (1.f / HID) + EPS);

    // LN pass 3: store h0 (pre-LN) and act (post LN+ReLU, fp16)
    const bool v_lo = (row_lo < n), v_hi = (row_hi < n);
    #pragma unroll
    for (int t = 0; t < 16; t++) {
        const int colp = t * 8 + (lane & 3) * 2;          // even column
        float2 sc = __ldg((const float2*)&lns[colp]);
        float2 bi = __ldg((const float2*)&lnb[colp]);
        if (v_lo) {
            *(float2*)&h0[(size_t)row_lo * HID + colp] = make_float2(c[t][0], c[t][1]);
            act[(size_t)row_lo * 64 + (colp >> 1)] = pack_h2(
                fmaxf((c[t][0] - mu_lo) * rstd_lo * sc.x + bi.x, 0.f),
                fmaxf((c[t][1] - mu_lo) * rstd_lo * sc.y + bi.y, 0.f));
        }
        if (v_hi) {
            *(float2*)&h0[(size_t)row_hi * HID + colp] = make_float2(c[t][2], c[t][3]);
            act[(size_t)row_hi * 64 + (colp >> 1)] = pack_h2(
                fmaxf((c[t][2] - mu_hi) * rstd_hi * sc.x + bi.x, 0.f),
                fmaxf((c[t][3] - mu_hi) * rstd_hi * sc.y + bi.y, 0.f));
        }
    }
}

// ---------------------------------------------------------------------------
// CSR build (unchanged from R8)
// ---------------------------------------------------------------------------
__global__ void hist_kernel(const int* __restrict__ dst, int* __restrict__ deg, int E)
{
    int e0 = (blockIdx.x * blockDim.x + threadIdx.x) * 4;
    if (e0 + 3 < E) {
        int4 d = *(const int4*)&dst[e0];
        atomicAdd(&deg[d.x], 1); atomicAdd(&deg[d.y], 1);
        atomicAdd(&deg[d.z], 1); atomicAdd(&deg[d.w], 1);
    } else {
        for (int e = e0; e < E; e++) atomicAdd(&deg[dst[e]], 1);
    }
}

__global__ void reduce_kernel(const int* __restrict__ deg,
                              int* __restrict__ bsum, int n)
{
    __shared__ int sh[256];
    const int t = threadIdx.x;
    const int base = blockIdx.x * CHUNK;
    int s = 0;
    #pragma unroll
    for (int j = 0; j < CHUNK / 256; j++) {
        int i = base + j * 256 + t;
        if (i < n) s += deg[i];
    }
    sh[t] = s;
    __syncthreads();
    #pragma unroll
    for (int o = 128; o > 0; o >>= 1) {
        if (t < o) sh[t] += sh[t + o];
        __syncthreads();
    }
    if (t == 0) bsum[blockIdx.x] = sh[0];
}

__global__ void scan_bsum_kernel(int* __restrict__ bsum, int nb)
{
    __shared__ int sh[128];
    const int t = threadIdx.x;
    int v = (t < nb) ? bsum[t] : 0;
    sh[t] = v;
    __syncthreads();
    for (int o = 1; o < 128; o <<= 1) {
        int u = (t >= o) ? sh[t - o] : 0;
        __syncthreads();
        sh[t] += u;
        __syncthreads();
    }
    if (t < nb) bsum[t] = sh[t] - v;        // exclusive
    if (t == nb - 1) bsum[nb] = sh[t];      // total
}

__global__ void write_off_kernel(const int* __restrict__ deg,
                                 const int* __restrict__ bsum,
                                 int* __restrict__ off,
                                 int* __restrict__ cur, int n, int nb)
{
    __shared__ int sh[256];
    const int t = threadIdx.x;
    const int base = blockIdx.x * CHUNK + t * 4;

    int d[4];
    #pragma unroll
    for (int j = 0; j < 4; j++)
        d[j] = (base + j < n) ? deg[base + j] : 0;

    int local = d[0] + d[1] + d[2] + d[3];
    sh[t] = local;
    __syncthreads();
    for (int o = 1; o < 256; o <<= 1) {
        int u = (t >= o) ? sh[t - o] : 0;
        __syncthreads();
        sh[t] += u;
        __syncthreads();
    }
    int run = bsum[blockIdx.x] + sh[t] - local;
    #pragma unroll
    for (int j = 0; j < 4; j++) {
        int i = base + j;
        if (i < n) { off[i] = run; cur[i] = run; run += d[j]; }
    }
    if (blockIdx.x == 0 && t == 0) off[n] = bsum[nb];
}

__global__ void fill_kernel(const int* __restrict__ src, const int* __restrict__ dst,
                            const float* __restrict__ ef,
                            int* __restrict__ cur, int2* __restrict__ srcw, int E)
{
    int e0 = (blockIdx.x * blockDim.x + threadIdx.x) * 4;
    if (e0 + 3 < E) {
        int4   s = *(const int4*)&src[e0];
        int4   d = *(const int4*)&dst[e0];
        float4 w = *(const float4*)&ef[e0];
        int p0 = atomicAdd(&cur[d.x], 1);
        int p1 = atomicAdd(&cur[d.y], 1);
        int p2 = atomicAdd(&cur[d.z], 1);
        int p3 = atomicAdd(&cur[d.w], 1);
        srcw[p0] = make_int2(s.x, __float_as_int(w.x));
        srcw[p1] = make_int2(s.y, __float_as_int(w.y));
        srcw[p2] = make_int2(s.z, __float_as_int(w.z));
        srcw[p3] = make_int2(s.w, __float_as_int(w.w));
    } else {
        for (int e = e0; e < E; e++) {
            int p = atomicAdd(&cur[dst[e]], 1);
            srcw[p] = make_int2(src[e], __float_as_int(ef[e]));
        }
    }
}

// ---------------------------------------------------------------------------
// SpMM gather-reduce over fp16 features (exact R8 version: warp/node, LDG.64,
// unroll 8), fp32 accumulation.
// ---------------------------------------------------------------------------
template <bool FUSE_LN>
__global__ void spmm_csr_kernel(const int* __restrict__ off,
                                const int2* __restrict__ srcw,
                                const uint2* __restrict__ hin,
                                const float4* __restrict__ h0,
                                const float* __restrict__ lns,
                                const float* __restrict__ lnb,
                                uint2* __restrict__ out_h,
                                float4* __restrict__ out_f, int n)
{
    const int node = blockIdx.x * 8 + (threadIdx.x >> 5);
    const int lane = threadIdx.x & 31;
    if (node >= n) return;

    const int beg = off[node];
    const int end = off[node + 1];

    float4 a = make_float4(0.f, 0.f, 0.f, 0.f);
    for (int base = beg; base < end; base += 32) {
        int cnt = min(end - base, 32);
        int2 sw = make_int2(0, 0);
        if (lane < cnt) sw = __ldg(&srcw[base + lane]);
        #pragma unroll 8
        for (int j = 0; j < cnt; j++) {
            int   s = __shfl_sync(0xffffffffu, sw.x, j);
            float w = __int_as_float(__shfl_sync(0xffffffffu, sw.y, j));
            uint2 p = __ldg(&hin[(size_t)s * 32 + lane]);
            float2 lo = __half22float2(*(half2*)&p.x);
            float2 hi = __half22float2(*(half2*)&p.y);
            a.x += lo.x * w; a.y += lo.y * w;
            a.z += hi.x * w; a.w += hi.y * w;
        }
    }

    if (FUSE_LN) {
        float4 r = __ldg(&h0[(size_t)node * 32 + lane]);
        a.x += r.x; a.y += r.y; a.z += r.z; a.w += r.w;

        float s = a.x + a.y + a.z + a.w;
        #pragma unroll
        for (int o = 16; o > 0; o >>= 1) s += __shfl_xor_sync(0xffffffffu, s, o);
        float mu = s * (1.f / HID);
        float dx = a.x - mu, dy = a.y - mu, dz = a.z - mu, dw = a.w - mu;
        float q = dx * dx + dy * dy + dz * dz + dw * dw;
        #pragma unroll
        for (int o = 16; o > 0; o >>= 1) q += __shfl_xor_sync(0xffffffffu, q, o);
        float rstd = rsqrtf(q * (1.f / HID) + EPS);

        int j0 = lane * 4;
        float4 sc = __ldg((const float4*)&lns[j0]);
        float4 bi = __ldg((const float4*)&lnb[j0]);
        out_h[(size_t)node * 32 + lane] = pack_h4(
            fmaxf(dx * rstd * sc.x + bi.x, 0.f),
            fmaxf(dy * rstd * sc.y + bi.y, 0.f),
            fmaxf(dz * rstd * sc.z + bi.z, 0.f),
            fmaxf(dw * rstd * sc.w + bi.w, 0.f));
    } else {
        out_f[(size_t)node * 32 + lane] = a;
    }
}

// ---------------------------------------------------------------------------
extern "C" void kernel_launch(void* const* d_in, const int* in_sizes, int n_in,
                              void* d_out, int out_size)
{
    const float* x   = (const float*)d_in[0];
    const int*   ei  = (const int*)d_in[1];     // [2, E] int32
    const float* ef  = (const float*)d_in[2];
    const float* W   = (const float*)d_in[3];
    const float* b   = (const float*)d_in[4];
    const float* lns = (const float*)d_in[5];
    const float* lnb = (const float*)d_in[6];

    const int n = in_sizes[0] / HID;
    const int E = in_sizes[2];
    float4* out = (float4*)d_out;

    float4 *h0; uint2 *act, *act2; int2* srcw; int *off, *cur, *deg, *bsum;
    cudaGetSymbolAddress((void**)&h0,   g_h0);
    cudaGetSymbolAddress((void**)&act,  g_act);
    cudaGetSymbolAddress((void**)&act2, g_act2);
    cudaGetSymbolAddress((void**)&srcw, g_srcw);
    cudaGetSymbolAddress((void**)&off,  g_off);
    cudaGetSymbolAddress((void**)&cur,  g_cur);
    cudaGetSymbolAddress((void**)&deg,  g_deg);
    cudaGetSymbolAddress((void**)&bsum, g_bsum);

    const int nb = (n + CHUNK - 1) / CHUNK;

    // 1. Tensor-core Linear + LN0 + ReLU (fused) with fused deg-zeroing blocks
    const int gemm_blocks = (n + 127) / 128;
    const int gemm_smem = 2 * 128 * GLDA * (int)sizeof(half);   // 69632 B
    cudaFuncSetAttribute(gemm_ln_kernel,
                         cudaFuncAttributeMaxDynamicSharedMemorySize, gemm_smem);
    gemm_ln_kernel<<<gemm_blocks + nb, 256, gemm_smem>>>(x, W, b, lns, lnb,
                                                         (float*)h0,
                                                         (unsigned*)act, deg,
                                                         n, gemm_blocks);

    // 2. CSR build (dst-grouped)
    hist_kernel<<<(E / 4 + 255) / 256, 256>>>(ei + E, deg, E);
    reduce_kernel<<<nb, 256>>>(deg, bsum, n);
    scan_bsum_kernel<<<1, 128>>>(bsum, nb);
    write_off_kernel<<<nb, 256>>>(deg, bsum, off, cur, n, nb);
    fill_kernel<<<(E / 4 + 255) / 256, 256>>>(ei, ei + E, ef, cur, srcw, E);

    // 3. Layer 0 aggregation + residual + LN1 + ReLU (fused), act2 in fp16
    const int spmm_blocks = (n + 7) / 8;
    spmm_csr_kernel<true><<<spmm_blocks, 256>>>(off, srcw, act, h0,
                                                lns + HID, lnb + HID,
                                                act2, nullptr, n);

    // 4. Layer 1 aggregation -> final fp32 output
    spmm_csr_kernel<false><<<spmm_blocks, 256>>>(off, srcw, act2, nullptr,
                                                 nullptr, nullptr,
                                                 nullptr, out, n);
}

// round 13
// speedup vs baseline: 1.2191x; 1.0094x over previous
#include <cuda_runtime.h>
#include <cuda_fp16.h>
#include <cstdint>

#define NMAX 100000
#define EMAX 1600000
#define HID 128
#define EPS 1e-5f
#define CHUNK 1024
#define NBLK ((NMAX + CHUNK - 1) / CHUNK)   // 98
#define GLDA 136    // smem row stride in halfs: 272B = 17 x 16B -> ldmatrix conflict-free

#define FLAG_PART 0x40000000u
#define FLAG_DONE 0x80000000u
#define VAL_MASK  0x3FFFFFFFu

// Scratch (no cudaMalloc allowed).
__device__ float4 g_h0  [(size_t)NMAX * HID / 4];  // post-linear ("ori"), fp32
__device__ uint2  g_act [(size_t)NMAX * HID / 4];  // layer-0 input, fp16
__device__ uint2  g_act2[(size_t)NMAX * HID / 4];  // layer-1 input, fp16
__device__ int2   g_srcw[EMAX];                    // CSR payload: (src, w-bits)
__device__ int    g_off [NMAX + 1];
__device__ int    g_cur [NMAX];
__device__ int    g_deg [NMAX + NBLK];             // deg + lookback state (one memset)

__device__ __forceinline__ unsigned pack_h2(float a, float b)
{
    half2 h = __floats2half2_rn(a, b);
    return *(unsigned*)&h;
}

__device__ __forceinline__ uint2 pack_h4(float a, float b, float c, float d)
{
    return make_uint2(pack_h2(a, b), pack_h2(c, d));
}

__device__ __forceinline__ uint32_t s2u(const void* p)
{
    uint32_t a;
    asm("{ .reg .u64 t; cvta.to.shared.u64 t, %1; cvt.u32.u64 %0, t; }"
        : "=r"(a) : "l"(p));
    return a;
}

__device__ __forceinline__ void ldm_x4(uint32_t* r, uint32_t addr)
{
    asm volatile("ldmatrix.sync.aligned.m8n8.x4.shared.b16 {%0,%1,%2,%3}, [%4];"
                 : "=r"(r[0]), "=r"(r[1]), "=r"(r[2]), "=r"(r[3]) : "r"(addr));
}

__device__ __forceinline__ void ldm_x2(uint32_t* r, uint32_t addr)
{
    asm volatile("ldmatrix.sync.aligned.m8n8.x2.shared.b16 {%0,%1}, [%2];"
                 : "=r"(r[0]), "=r"(r[1]) : "r"(addr));
}

__device__ __forceinline__ void mma16816(float* c, const uint32_t* a, const uint32_t* b)
{
    asm volatile("mma.sync.aligned.m16n8k16.row.col.f32.f16.f16.f32 "
                 "{%0,%1,%2,%3}, {%4,%5,%6,%7}, {%8,%9}, {%0,%1,%2,%3};"
                 : "+f"(c[0]), "+f"(c[1]), "+f"(c[2]), "+f"(c[3])
                 : "r"(a[0]), "r"(a[1]), "r"(a[2]), "r"(a[3]),
                   "r"(b[0]), "r"(b[1]));
}

// ---------------------------------------------------------------------------
// Tensor-core GEMM (fp16 in, fp32 accum) + bias + fused LN0 + ReLU epilogue.
// Launched with PDL (no device sync needed: fully independent of CSR build).
// ---------------------------------------------------------------------------
extern __shared__ char smem_raw[];
__global__ void gemm_ln_kernel(const float* __restrict__ x,
                               const float* __restrict__ W,
                               const float* __restrict__ b,
                               const float* __restrict__ lns,
                               const float* __restrict__ lnb,
                               float* __restrict__ h0,
                               unsigned* __restrict__ act,
                               int n)
{
    half* ws = (half*)smem_raw;               // [128][GLDA] fp16 W
    half* xs = ws + 128 * GLDA;               // [128][GLDA] fp16 x tile
    const int tid  = threadIdx.x;
    const int lane = tid & 31;
    const int warp = tid >> 5;                // 0..7
    const int row0 = blockIdx.x * 128;

    for (int idx = tid; idx < HID * HID; idx += 256) {
        int j = idx >> 7, k = idx & 127;
        ws[j * GLDA + k] = __float2half(W[idx]);
    }
    for (int idx = tid; idx < 128 * HID; idx += 256) {
        int r = idx >> 7, k = idx & 127;
        int row = row0 + r;
        xs[r * GLDA + k] = (row < n) ? __float2half(x[(size_t)row * HID + k])
                                     : __half(0.f);
    }
    __syncthreads();

    const uint32_t xs_u = s2u(xs);
    const uint32_t ws_u = s2u(ws);

    float c[16][4];
    #pragma unroll
    for (int t = 0; t < 16; t++)
        #pragma unroll
        for (int i = 0; i < 4; i++) c[t][i] = 0.f;

    const uint32_t a_base = xs_u +
        (uint32_t)(((warp * 16 + (lane & 15)) * GLDA + ((lane >> 4) << 3)) * 2);
    const uint32_t b_base = ws_u +
        (uint32_t)((((lane & 7)) * GLDA + (((lane >> 3) & 1) << 3)) * 2);

    #pragma unroll
    for (int ks = 0; ks < 8; ks++) {
        const uint32_t koff = ks * 16 * 2;
        uint32_t a[4];
        ldm_x4(a, a_base + koff);
        #pragma unroll
        for (int t = 0; t < 16; t++) {
            uint32_t bf[2];
            ldm_x2(bf, b_base + (uint32_t)(t * 8 * GLDA * 2) + koff);
            mma16816(c[t], a, bf);
        }
    }

    #pragma unroll
    for (int t = 0; t < 16; t++) {
        float2 bb = __ldg((const float2*)&b[t * 8 + (lane & 3) * 2]);
        c[t][0] += bb.x; c[t][1] += bb.y;
        c[t][2] += bb.x; c[t][3] += bb.y;
    }

    const int row_lo = row0 + warp * 16 + (lane >> 2);
    const int row_hi = row_lo + 8;

    float s_lo = 0.f, s_hi = 0.f;
    #pragma unroll
    for (int t = 0; t < 16; t++) {
        s_lo += c[t][0] + c[t][1];
        s_hi += c[t][2] + c[t][3];
    }
    s_lo += __shfl_xor_sync(0xffffffffu, s_lo, 1);
    s_lo += __shfl_xor_sync(0xffffffffu, s_lo, 2);
    s_hi += __shfl_xor_sync(0xffffffffu, s_hi, 1);
    s_hi += __shfl_xor_sync(0xffffffffu, s_hi, 2);
    const float mu_lo = s_lo * (1.f / HID);
    const float mu_hi = s_hi * (1.f / HID);

    float q_lo = 0.f, q_hi = 0.f;
    #pragma unroll
    for (int t = 0; t < 16; t++) {
        float d0 = c[t][0] - mu_lo, d1 = c[t][1] - mu_lo;
        float d2 = c[t][2] - mu_hi, d3 = c[t][3] - mu_hi;
        q_lo += d0 * d0 + d1 * d1;
        q_hi += d2 * d2 + d3 * d3;
    }
    q_lo += __shfl_xor_sync(0xffffffffu, q_lo, 1);
    q_lo += __shfl_xor_sync(0xffffffffu, q_lo, 2);
    q_hi += __shfl_xor_sync(0xffffffffu, q_hi, 1);
    q_hi += __shfl_xor_sync(0xffffffffu, q_hi, 2);
    const float rstd_lo = rsqrtf(q_lo * (1.f / HID) + EPS);
    const float rstd_hi = rsqrtf(q_hi * (1.f / HID) + EPS);

    const bool v_lo = (row_lo < n), v_hi = (row_hi < n);
    #pragma unroll
    for (int t = 0; t < 16; t++) {
        const int colp = t * 8 + (lane & 3) * 2;
        float2 sc = __ldg((const float2*)&lns[colp]);
        float2 bi = __ldg((const float2*)&lnb[colp]);
        if (v_lo) {
            *(float2*)&h0[(size_t)row_lo * HID + colp] = make_float2(c[t][0], c[t][1]);
            act[(size_t)row_lo * 64 + (colp >> 1)] = pack_h2(
                fmaxf((c[t][0] - mu_lo) * rstd_lo * sc.x + bi.x, 0.f),
                fmaxf((c[t][1] - mu_lo) * rstd_lo * sc.y + bi.y, 0.f));
        }
        if (v_hi) {
            *(float2*)&h0[(size_t)row_hi * HID + colp] = make_float2(c[t][2], c[t][3]);
            act[(size_t)row_hi * 64 + (colp >> 1)] = pack_h2(
                fmaxf((c[t][2] - mu_hi) * rstd_hi * sc.x + bi.x, 0.f),
                fmaxf((c[t][3] - mu_hi) * rstd_hi * sc.y + bi.y, 0.f));
        }
    }
}

// ---------------------------------------------------------------------------
// CSR build.  hist: PDL — load input quad, sync on memset, then atomics.
// ---------------------------------------------------------------------------
__global__ void hist_kernel(const int* __restrict__ dst, int* __restrict__ deg, int E)
{
    int e0 = (blockIdx.x * blockDim.x + threadIdx.x) * 4;
    if (e0 + 3 < E) {
        int4 d = *(const int4*)&dst[e0];
        cudaGridDependencySynchronize();
        atomicAdd(&deg[d.x], 1); atomicAdd(&deg[d.y], 1);
        atomicAdd(&deg[d.z], 1); atomicAdd(&deg[d.w], 1);
    } else {
        cudaGridDependencySynchronize();
        for (int e = e0; e < E; e++) atomicAdd(&deg[dst[e]], 1);
    }
}

// Single-pass exclusive scan of deg -> off/cur via decoupled lookback.
// state[] (deg+NMAX) zeroed by the same memset as deg.
__global__ void scan_kernel(const int* __restrict__ deg,
                            unsigned* __restrict__ state,
                            int* __restrict__ off,
                            int* __restrict__ cur, int n, int nb)
{
    cudaGridDependencySynchronize();          // wait for hist (PDL launch)
    __shared__ int sh[256];
    __shared__ int s_base;
    const int t   = threadIdx.x;
    const int bid = blockIdx.x;
    const int base = bid * CHUNK + t * 4;

    int d[4];
    #pragma unroll
    for (int j = 0; j < 4; j++)
        d[j] = (base + j < n) ? deg[base + j] : 0;
    int local = d[0] + d[1] + d[2] + d[3];

    sh[t] = local;
    __syncthreads();
    for (int o = 1; o < 256; o <<= 1) {       // inclusive Hillis-Steele
        int u = (t >= o) ? sh[t - o] : 0;
        __syncthreads();
        sh[t] += u;
        __syncthreads();
    }

    if (t == 0) {
        unsigned agg = (unsigned)sh[255];
        int run = 0;
        if (bid == 0) {
            atomicExch(&state[0], agg | FLAG_DONE);
        } else {
            atomicExch(&state[bid], agg | FLAG_PART);
            int p = bid - 1;
            for (;;) {
                unsigned s;
                do { s = atomicAdd(&state[p], 0u); } while (s == 0u);
                run += (int)(s & VAL_MASK);
                if (s & FLAG_DONE) break;
                p--;
            }
            atomicExch(&state[bid], ((unsigned)run + agg) | FLAG_DONE);
        }
        s_base = run;
        if (bid == nb - 1) off[n] = run + (int)agg;
    }
    __syncthreads();

    int run = s_base + sh[t] - local;         // exclusive base for elem 0
    #pragma unroll
    for (int j = 0; j < 4; j++) {
        int i = base + j;
        if (i < n) { off[i] = run; cur[i] = run; run += d[j]; }
    }
}

__global__ void fill_kernel(const int* __restrict__ src, const int* __restrict__ dst,
                            const float* __restrict__ ef,
                            int* __restrict__ cur, int2* __restrict__ srcw, int E)
{
    int e0 = (blockIdx.x * blockDim.x + threadIdx.x) * 4;
    if (e0 + 3 < E) {
        int4   s = *(const int4*)&src[e0];
        int4   d = *(const int4*)&dst[e0];
        float4 w = *(const float4*)&ef[e0];
        cudaGridDependencySynchronize();       // wait scan (cur ready)
        int p0 = atomicAdd(&cur[d.x], 1);
        int p1 = atomicAdd(&cur[d.y], 1);
        int p2 = atomicAdd(&cur[d.z], 1);
        int p3 = atomicAdd(&cur[d.w], 1);
        srcw[p0] = make_int2(s.x, __float_as_int(w.x));
        srcw[p1] = make_int2(s.y, __float_as_int(w.y));
        srcw[p2] = make_int2(s.z, __float_as_int(w.z));
        srcw[p3] = make_int2(s.w, __float_as_int(w.w));
    } else {
        cudaGridDependencySynchronize();
        for (int e = e0; e < E; e++) {
            int p = atomicAdd(&cur[dst[e]], 1);
            srcw[p] = make_int2(src[e], __float_as_int(ef[e]));
        }
    }
}

// ---------------------------------------------------------------------------
// SpMM gather-reduce over fp16 features, fp32 accumulation (R8 structure).
// PDL variant (spmm1): prefetch off + first srcw batch (stable: written
// before spmm0, which is a plain full-barrier launch), sync, then gather.
// ---------------------------------------------------------------------------
template <bool FUSE_LN, bool PDL>
__global__ void spmm_csr_kernel(const int* __restrict__ off,
                                const int2* __restrict__ srcw,
                                const uint2* __restrict__ hin,
                                const float4* __restrict__ h0,
                                const float* __restrict__ lns,
                                const float* __restrict__ lnb,
                                uint2* __restrict__ out_h,
                                float4* __restrict__ out_f, int n)
{
    const int node = blockIdx.x * 8 + (threadIdx.x >> 5);
    const int lane = threadIdx.x & 31;
    if (node >= n) {
        if (PDL) cudaGridDependencySynchronize();
        return;
    }

    const int beg = off[node];
    const int end = off[node + 1];

    int cnt = min(end - beg, 32);
    int2 sw = make_int2(0, 0);
    if (lane < cnt) sw = __ldg(&srcw[beg + lane]);

    if (PDL) cudaGridDependencySynchronize();  // wait for feature producer

    float4 a = make_float4(0.f, 0.f, 0.f, 0.f);
    for (int base = beg; base < end; base += 32) {
        #pragma unroll 8
        for (int j = 0; j < cnt; j++) {
            int   s = __shfl_sync(0xffffffffu, sw.x, j);
            float w = __int_as_float(__shfl_sync(0xffffffffu, sw.y, j));
            uint2 p = __ldg(&hin[(size_t)s * 32 + lane]);
            float2 lo = __half22float2(*(half2*)&p.x);
            float2 hi = __half22float2(*(half2*)&p.y);
            a.x += lo.x * w; a.y += lo.y * w;
            a.z += hi.x * w; a.w += hi.y * w;
        }
        int nb2 = base + 32;
        if (nb2 < end) {
            cnt = min(end - nb2, 32);
            sw = make_int2(0, 0);
            if (lane < cnt) sw = __ldg(&srcw[nb2 + lane]);
        }
    }

    if (FUSE_LN) {
        float4 r = __ldg(&h0[(size_t)node * 32 + lane]);
        a.x += r.x; a.y += r.y; a.z += r.z; a.w += r.w;

        float s = a.x + a.y + a.z + a.w;
        #pragma unroll
        for (int o = 16; o > 0; o >>= 1) s += __shfl_xor_sync(0xffffffffu, s, o);
        float mu = s * (1.f / HID);
        float dx = a.x - mu, dy = a.y - mu, dz = a.z - mu, dw = a.w - mu;
        float q = dx * dx + dy * dy + dz * dz + dw * dw;
        #pragma unroll
        for (int o = 16; o > 0; o >>= 1) q += __shfl_xor_sync(0xffffffffu, q, o);
        float rstd = rsqrtf(q * (1.f / HID) + EPS);

        int j0 = lane * 4;
        float4 sc = __ldg((const float4*)&lns[j0]);
        float4 bi = __ldg((const float4*)&lnb[j0]);
        out_h[(size_t)node * 32 + lane] = pack_h4(
            fmaxf(dx * rstd * sc.x + bi.x, 0.f),
            fmaxf(dy * rstd * sc.y + bi.y, 0.f),
            fmaxf(dz * rstd * sc.z + bi.z, 0.f),
            fmaxf(dw * rstd * sc.w + bi.w, 0.f));
    } else {
        out_f[(size_t)node * 32 + lane] = a;
    }
}

// ---------------------------------------------------------------------------
extern "C" void kernel_launch(void* const* d_in, const int* in_sizes, int n_in,
                              void* d_out, int out_size)
{
    const float* x   = (const float*)d_in[0];
    const int*   ei  = (const int*)d_in[1];     // [2, E] int32
    const float* ef  = (const float*)d_in[2];
    const float* W   = (const float*)d_in[3];
    const float* b   = (const float*)d_in[4];
    const float* lns = (const float*)d_in[5];
    const float* lnb = (const float*)d_in[6];

    const int n = in_sizes[0] / HID;
    const int E = in_sizes[2];
    float4* out = (float4*)d_out;

    float4 *h0; uint2 *act, *act2; int2* srcw; int *off, *cur, *deg;
    cudaGetSymbolAddress((void**)&h0,   g_h0);
    cudaGetSymbolAddress((void**)&act,  g_act);
    cudaGetSymbolAddress((void**)&act2, g_act2);
    cudaGetSymbolAddress((void**)&srcw, g_srcw);
    cudaGetSymbolAddress((void**)&off,  g_off);
    cudaGetSymbolAddress((void**)&cur,  g_cur);
    cudaGetSymbolAddress((void**)&deg,  g_deg);
    unsigned* state = (unsigned*)(deg + NMAX);

    const int nb = (n + CHUNK - 1) / CHUNK;

    cudaLaunchAttribute pa[1];
    pa[0].id = cudaLaunchAttributeProgrammaticStreamSerialization;
    pa[0].val.programmaticStreamSerializationAllowed = 1;

    cudaLaunchConfig_t cfg{};
    cfg.blockDim = dim3(256);
    cfg.dynamicSmemBytes = 0;
    cfg.stream = 0;
    cfg.attrs = pa;
    cfg.numAttrs = 1;

    // 0. Zero deg + lookback state (one memset)
    cudaMemsetAsync(deg, 0, (size_t)(NMAX + NBLK) * sizeof(int), 0);

    // 1. CSR build chain (PDL: each stage's input loads overlap its predecessor)
    cfg.gridDim = dim3((E / 4 + 255) / 256);
    cudaLaunchKernelEx(&cfg, hist_kernel, ei + E, deg, E);

    cfg.gridDim = dim3(nb);
    cudaLaunchKernelEx(&cfg, scan_kernel, (const int*)deg, state, off, cur, n, nb);

    cfg.gridDim = dim3((E / 4 + 255) / 256);
    cudaLaunchKernelEx(&cfg, fill_kernel, ei, ei + E, ef, cur, srcw, E);

    // 2. Tensor-core Linear + LN0 + ReLU — PDL, fully independent of CSR build,
    //    overlaps fill (no device-side sync in the kernel).
    const int gemm_blocks = (n + 127) / 128;
    const int gemm_smem = 2 * 128 * GLDA * (int)sizeof(half);   // 69632 B
    cudaFuncSetAttribute(gemm_ln_kernel,
                         cudaFuncAttributeMaxDynamicSharedMemorySize, gemm_smem);
    cfg.gridDim = dim3(gemm_blocks);
    cfg.dynamicSmemBytes = gemm_smem;
    cudaLaunchKernelEx(&cfg, gemm_ln_kernel, x, W, b, lns, lnb,
                       (float*)h0, (unsigned*)act, n);
    cfg.dynamicSmemBytes = 0;

    // 3. Layer 0 aggregation + residual + LN1 + ReLU — plain launch (full
    //    barrier: needs gemm + CSR complete).
    const int spmm_blocks = (n + 7) / 8;
    spmm_csr_kernel<true, false><<<spmm_blocks, 256>>>(off, srcw, act, h0,
                                                       lns + HID, lnb + HID,
                                                       act2, nullptr, n);

    // 4. Layer 1 aggregation -> final fp32 output — PDL: prefetch off/srcw
    //    (stable since before spmm0), sync, then gather act2.
    cfg.gridDim = dim3(spmm_blocks);
    cudaLaunchKernelEx(&cfg, spmm_csr_kernel<false, true>,
                       (const int*)off, (const int2*)srcw, (const uint2*)act2,
                       (const float4*)nullptr, (const float*)nullptr,
                       (const float*)nullptr, (uint2*)nullptr, out, n);
}

// round 14
// speedup vs baseline: 1.5212x; 1.2478x over previous
#include <cuda_runtime.h>
#include <cuda_fp16.h>
#include <cstdint>

#define NMAX 100000
#define EMAX 1600000
#define HID 128
#define EPS 1e-5f
#define CHUNK 1024
#define NBLK ((NMAX + CHUNK - 1) / CHUNK)   // 98
#define GLDA 136    // smem row stride in halfs: 272B = 17 x 16B -> ldmatrix conflict-free

#define FLAG_PART 0x40000000u
#define FLAG_DONE 0x80000000u
#define VAL_MASK  0x3FFFFFFFu

// Scratch (no cudaMalloc allowed).
__device__ float4 g_h0  [(size_t)NMAX * HID / 4];  // post-linear ("ori"), fp32
__device__ uint2  g_act [(size_t)NMAX * HID / 4];  // layer-0 input, fp16
__device__ uint2  g_act2[(size_t)NMAX * HID / 4];  // layer-1 input, fp16
__device__ int2   g_srcw[EMAX];                    // CSR payload: (src, w-bits)
__device__ int    g_off [NMAX + 1];
__device__ int    g_cur [NMAX];
__device__ int    g_deg [NMAX + NBLK];             // deg + lookback state (one memset)

__device__ __forceinline__ unsigned pack_h2(float a, float b)
{
    half2 h = __floats2half2_rn(a, b);
    return *(unsigned*)&h;
}

__device__ __forceinline__ uint2 pack_h4(float a, float b, float c, float d)
{
    return make_uint2(pack_h2(a, b), pack_h2(c, d));
}

__device__ __forceinline__ uint32_t s2u(const void* p)
{
    uint32_t a;
    asm("{ .reg .u64 t; cvta.to.shared.u64 t, %1; cvt.u32.u64 %0, t; }"
        : "=r"(a) : "l"(p));
    return a;
}

__device__ __forceinline__ void ldm_x4(uint32_t* r, uint32_t addr)
{
    asm volatile("ldmatrix.sync.aligned.m8n8.x4.shared.b16 {%0,%1,%2,%3}, [%4];"
                 : "=r"(r[0]), "=r"(r[1]), "=r"(r[2]), "=r"(r[3]) : "r"(addr));
}

__device__ __forceinline__ void mma16816(float* c, const uint32_t* a, const uint32_t* b)
{
    asm volatile("mma.sync.aligned.m16n8k16.row.col.f32.f16.f16.f32 "
                 "{%0,%1,%2,%3}, {%4,%5,%6,%7}, {%8,%9}, {%0,%1,%2,%3};"
                 : "+f"(c[0]), "+f"(c[1]), "+f"(c[2]), "+f"(c[3])
                 : "r"(a[0]), "r"(a[1]), "r"(a[2]), "r"(a[3]),
                   "r"(b[0]), "r"(b[1]));
}

// ---------------------------------------------------------------------------
// Tensor-core GEMM (fp16 in, fp32 accum) + bias + fused LN0 + ReLU epilogue.
// 512 threads / 16 warps; block tile 128x128; warp tile 16 rows x 64 cols
// (warp w: rows (w>>1)*16, cols (w&1)*64).  Per k-step: 1 ldm_x4 A-frag +
// 4 independent ldm_x4 B-frags + 8 mmas.  LN row moments (E[x], E[x^2])
// combined across the col-pair warps via a smem slab (reuses staging smem).
// ---------------------------------------------------------------------------
extern __shared__ char smem_raw[];
__global__ void __launch_bounds__(512)
gemm_ln_kernel(const float* __restrict__ x,
               const float* __restrict__ W,
               const float* __restrict__ b,
               const float* __restrict__ lns,
               const float* __restrict__ lnb,
               float* __restrict__ h0,
               unsigned* __restrict__ act,
               int n)
{
    half* ws = (half*)smem_raw;               // [128][GLDA] fp16 W
    half* xs = ws + 128 * GLDA;               // [128][GLDA] fp16 x tile
    const int tid  = threadIdx.x;
    const int lane = tid & 31;
    const int warp = tid >> 5;                // 0..15
    const int wr   = warp >> 1;               // row group 0..7
    const int cg   = warp & 1;                // col group 0..1
    const int row0 = blockIdx.x * 128;

    for (int idx = tid; idx < HID * HID; idx += 512) {
        int j = idx >> 7, k = idx & 127;
        ws[j * GLDA + k] = __float2half(W[idx]);
    }
    for (int idx = tid; idx < 128 * HID; idx += 512) {
        int r = idx >> 7, k = idx & 127;
        int row = row0 + r;
        xs[r * GLDA + k] = (row < n) ? __float2half(x[(size_t)row * HID + k])
                                     : __half(0.f);
    }
    __syncthreads();

    const uint32_t xs_u = s2u(xs);
    const uint32_t ws_u = s2u(ws);

    float c[8][4];
    #pragma unroll
    for (int t = 0; t < 8; t++)
        #pragma unroll
        for (int i = 0; i < 4; i++) c[t][i] = 0.f;

    // A-frag: row = wr*16 + (lane&15), col-half = (lane>>4)*8
    const uint32_t a_base = xs_u +
        (uint32_t)(((wr * 16 + (lane & 15)) * GLDA + ((lane >> 4) << 3)) * 2);
    // B-frag x4 (two n8-tiles per load): n-row = cg*64 + tp*16 + ((lane>>4)<<3)
    // + (lane&7); k-half = ((lane>>3)&1)*8
    const uint32_t b_base = ws_u +
        (uint32_t)(((cg * 64 + ((lane >> 4) << 3) + (lane & 7)) * GLDA +
                    (((lane >> 3) & 1) << 3)) * 2);

    #pragma unroll
    for (int ks = 0; ks < 8; ks++) {
        const uint32_t koff = ks * 16 * 2;    // bytes
        uint32_t a[4];
        ldm_x4(a, a_base + koff);
        uint32_t bf[4][4];
        #pragma unroll
        for (int tp = 0; tp < 4; tp++)
            ldm_x4(bf[tp], b_base + (uint32_t)(tp * 16 * GLDA * 2) + koff);
        #pragma unroll
        for (int tp = 0; tp < 4; tp++) {
            mma16816(c[2 * tp + 0], a, &bf[tp][0]);
            mma16816(c[2 * tp + 1], a, &bf[tp][2]);
        }
    }

    // Bias (cols for frag t: cg*64 + t*8 + (lane&3)*2)
    #pragma unroll
    for (int t = 0; t < 8; t++) {
        float2 bb = __ldg((const float2*)&b[cg * 64 + t * 8 + (lane & 3) * 2]);
        c[t][0] += bb.x; c[t][1] += bb.y;
        c[t][2] += bb.x; c[t][3] += bb.y;
    }

    // Row moments over this warp's 64 cols: s = sum, q = sum of squares
    float s_lo = 0.f, s_hi = 0.f, q_lo = 0.f, q_hi = 0.f;
    #pragma unroll
    for (int t = 0; t < 8; t++) {
        s_lo += c[t][0] + c[t][1];
        s_hi += c[t][2] + c[t][3];
        q_lo += c[t][0] * c[t][0] + c[t][1] * c[t][1];
        q_hi += c[t][2] * c[t][2] + c[t][3] * c[t][3];
    }
    #pragma unroll
    for (int o = 1; o <= 2; o <<= 1) {
        s_lo += __shfl_xor_sync(0xffffffffu, s_lo, o);
        s_hi += __shfl_xor_sync(0xffffffffu, s_hi, o);
        q_lo += __shfl_xor_sync(0xffffffffu, q_lo, o);
        q_hi += __shfl_xor_sync(0xffffffffu, q_hi, o);
    }

    // Combine the two col-group warps via smem (reuse staging area after sync)
    float2* red = (float2*)smem_raw;          // [128][2]
    __syncthreads();                          // everyone done reading ws/xs
    const int lrow_lo = wr * 16 + (lane >> 2);
    if ((lane & 3) == 0) {
        red[lrow_lo * 2 + cg]       = make_float2(s_lo, q_lo);
        red[(lrow_lo + 8) * 2 + cg] = make_float2(s_hi, q_hi);
    }
    __syncthreads();
    float2 m0 = red[lrow_lo * 2 + 0],       m1 = red[lrow_lo * 2 + 1];
    float2 n0 = red[(lrow_lo + 8) * 2 + 0], n1 = red[(lrow_lo + 8) * 2 + 1];
    const float mu_lo   = (m0.x + m1.x) * (1.f / HID);
    const float mu_hi   = (n0.x + n1.x) * (1.f / HID);
    const float rstd_lo = rsqrtf(fmaxf((m0.y + m1.y) * (1.f / HID) - mu_lo * mu_lo, 0.f) + EPS);
    const float rstd_hi = rsqrtf(fmaxf((n0.y + n1.y) * (1.f / HID) - mu_hi * mu_hi, 0.f) + EPS);

    const int row_lo = row0 + lrow_lo;
    const int row_hi = row_lo + 8;
    const bool v_lo = (row_lo < n), v_hi = (row_hi < n);
    #pragma unroll
    for (int t = 0; t < 8; t++) {
        const int colp = cg * 64 + t * 8 + (lane & 3) * 2;
        float2 sc = __ldg((const float2*)&lns[colp]);
        float2 bi = __ldg((const float2*)&lnb[colp]);
        if (v_lo) {
            *(float2*)&h0[(size_t)row_lo * HID + colp] = make_float2(c[t][0], c[t][1]);
            act[(size_t)row_lo * 64 + (colp >> 1)] = pack_h2(
                fmaxf((c[t][0] - mu_lo) * rstd_lo * sc.x + bi.x, 0.f),
                fmaxf((c[t][1] - mu_lo) * rstd_lo * sc.y + bi.y, 0.f));
        }
        if (v_hi) {
            *(float2*)&h0[(size_t)row_hi * HID + colp] = make_float2(c[t][2], c[t][3]);
            act[(size_t)row_hi * 64 + (colp >> 1)] = pack_h2(
                fmaxf((c[t][2] - mu_hi) * rstd_hi * sc.x + bi.x, 0.f),
                fmaxf((c[t][3] - mu_hi) * rstd_hi * sc.y + bi.y, 0.f));
        }
    }
}

// ---------------------------------------------------------------------------
// CSR build.  hist: PDL — load input quad, sync on memset, then atomics.
// ---------------------------------------------------------------------------
__global__ void hist_kernel(const int* __restrict__ dst, int* __restrict__ deg, int E)
{
    int e0 = (blockIdx.x * blockDim.x + threadIdx.x) * 4;
    if (e0 + 3 < E) {
        int4 d = *(const int4*)&dst[e0];
        cudaGridDependencySynchronize();
        atomicAdd(&deg[d.x], 1); atomicAdd(&deg[d.y], 1);
        atomicAdd(&deg[d.z], 1); atomicAdd(&deg[d.w], 1);
    } else {
        cudaGridDependencySynchronize();
        for (int e = e0; e < E; e++) atomicAdd(&deg[dst[e]], 1);
    }
}

// Single-pass exclusive scan of deg -> off/cur via decoupled lookback.
__global__ void scan_kernel(const int* __restrict__ deg,
                            unsigned* __restrict__ state,
                            int* __restrict__ off,
                            int* __restrict__ cur, int n, int nb)
{
    cudaGridDependencySynchronize();          // wait for hist (PDL launch)
    __shared__ int sh[256];
    __shared__ int s_base;
    const int t   = threadIdx.x;
    const int bid = blockIdx.x;
    const int base = bid * CHUNK + t * 4;

    int d[4];
    #pragma unroll
    for (int j = 0; j < 4; j++)
        d[j] = (base + j < n) ? deg[base + j] : 0;
    int local = d[0] + d[1] + d[2] + d[3];

    sh[t] = local;
    __syncthreads();
    for (int o = 1; o < 256; o <<= 1) {       // inclusive Hillis-Steele
        int u = (t >= o) ? sh[t - o] : 0;
        __syncthreads();
        sh[t] += u;
        __syncthreads();
    }

    if (t == 0) {
        unsigned agg = (unsigned)sh[255];
        int run = 0;
        if (bid == 0) {
            atomicExch(&state[0], agg | FLAG_DONE);
        } else {
            atomicExch(&state[bid], agg | FLAG_PART);
            int p = bid - 1;
            for (;;) {
                unsigned s;
                do { s = atomicAdd(&state[p], 0u); } while (s == 0u);
                run += (int)(s & VAL_MASK);
                if (s & FLAG_DONE) break;
                p--;
            }
            atomicExch(&state[bid], ((unsigned)run + agg) | FLAG_DONE);
        }
        s_base = run;
        if (bid == nb - 1) off[n] = run + (int)agg;
    }
    __syncthreads();

    int run = s_base + sh[t] - local;         // exclusive base for elem 0
    #pragma unroll
    for (int j = 0; j < 4; j++) {
        int i = base + j;
        if (i < n) { off[i] = run; cur[i] = run; run += d[j]; }
    }
}

__global__ void fill_kernel(const int* __restrict__ src, const int* __restrict__ dst,
                            const float* __restrict__ ef,
                            int* __restrict__ cur, int2* __restrict__ srcw, int E)
{
    int e0 = (blockIdx.x * blockDim.x + threadIdx.x) * 4;
    if (e0 + 3 < E) {
        int4   s = *(const int4*)&src[e0];
        int4   d = *(const int4*)&dst[e0];
        float4 w = *(const float4*)&ef[e0];
        cudaGridDependencySynchronize();       // wait scan (cur ready)
        int p0 = atomicAdd(&cur[d.x], 1);
        int p1 = atomicAdd(&cur[d.y], 1);
        int p2 = atomicAdd(&cur[d.z], 1);
        int p3 = atomicAdd(&cur[d.w], 1);
        srcw[p0] = make_int2(s.x, __float_as_int(w.x));
        srcw[p1] = make_int2(s.y, __float_as_int(w.y));
        srcw[p2] = make_int2(s.z, __float_as_int(w.z));
        srcw[p3] = make_int2(s.w, __float_as_int(w.w));
    } else {
        cudaGridDependencySynchronize();
        for (int e = e0; e < E; e++) {
            int p = atomicAdd(&cur[dst[e]], 1);
            srcw[p] = make_int2(src[e], __float_as_int(ef[e]));
        }
    }
}

// ---------------------------------------------------------------------------
// SpMM gather-reduce over fp16 features, fp32 accumulation (R8 structure).
// ---------------------------------------------------------------------------
template <bool FUSE_LN, bool PDL>
__global__ void spmm_csr_kernel(const int* __restrict__ off,
                                const int2* __restrict__ srcw,
                                const uint2* __restrict__ hin,
                                const float4* __restrict__ h0,
                                const float* __restrict__ lns,
                                const float* __restrict__ lnb,
                                uint2* __restrict__ out_h,
                                float4* __restrict__ out_f, int n)
{
    const int node = blockIdx.x * 8 + (threadIdx.x >> 5);
    const int lane = threadIdx.x & 31;
    if (node >= n) {
        if (PDL) cudaGridDependencySynchronize();
        return;
    }

    const int beg = off[node];
    const int end = off[node + 1];

    int cnt = min(end - beg, 32);
    int2 sw = make_int2(0, 0);
    if (lane < cnt) sw = __ldg(&srcw[beg + lane]);

    if (PDL) cudaGridDependencySynchronize();  // wait for feature producer

    float4 a = make_float4(0.f, 0.f, 0.f, 0.f);
    for (int base = beg; base < end; base += 32) {
        #pragma unroll 8
        for (int j = 0; j < cnt; j++) {
            int   s = __shfl_sync(0xffffffffu, sw.x, j);
            float w = __int_as_float(__shfl_sync(0xffffffffu, sw.y, j));
            uint2 p = __ldg(&hin[(size_t)s * 32 + lane]);
            float2 lo = __half22float2(*(half2*)&p.x);
            float2 hi = __half22float2(*(half2*)&p.y);
            a.x += lo.x * w; a.y += lo.y * w;
            a.z += hi.x * w; a.w += hi.y * w;
        }
        int nb2 = base + 32;
        if (nb2 < end) {
            cnt = min(end - nb2, 32);
            sw = make_int2(0, 0);
            if (lane < cnt) sw = __ldg(&srcw[nb2 + lane]);
        }
    }

    if (FUSE_LN) {
        float4 r = __ldg(&h0[(size_t)node * 32 + lane]);
        a.x += r.x; a.y += r.y; a.z += r.z; a.w += r.w;

        float s = a.x + a.y + a.z + a.w;
        #pragma unroll
        for (int o = 16; o > 0; o >>= 1) s += __shfl_xor_sync(0xffffffffu, s, o);
        float mu = s * (1.f / HID);
        float dx = a.x - mu, dy = a.y - mu, dz = a.z - mu, dw = a.w - mu;
        float q = dx * dx + dy * dy + dz * dz + dw * dw;
        #pragma unroll
        for (int o = 16; o > 0; o >>= 1) q += __shfl_xor_sync(0xffffffffu, q, o);
        float rstd = rsqrtf(q * (1.f / HID) + EPS);

        int j0 = lane * 4;
        float4 sc = __ldg((const float4*)&lns[j0]);
        float4 bi = __ldg((const float4*)&lnb[j0]);
        out_h[(size_t)node * 32 + lane] = pack_h4(
            fmaxf(dx * rstd * sc.x + bi.x, 0.f),
            fmaxf(dy * rstd * sc.y + bi.y, 0.f),
            fmaxf(dz * rstd * sc.z + bi.z, 0.f),
            fmaxf(dw * rstd * sc.w + bi.w, 0.f));
    } else {
        out_f[(size_t)node * 32 + lane] = a;
    }
}

// ---------------------------------------------------------------------------
extern "C" void kernel_launch(void* const* d_in, const int* in_sizes, int n_in,
                              void* d_out, int out_size)
{
    const float* x   = (const float*)d_in[0];
    const int*   ei  = (const int*)d_in[1];     // [2, E] int32
    const float* ef  = (const float*)d_in[2];
    const float* W   = (const float*)d_in[3];
    const float* b   = (const float*)d_in[4];
    const float* lns = (const float*)d_in[5];
    const float* lnb = (const float*)d_in[6];

    const int n = in_sizes[0] / HID;
    const int E = in_sizes[2];
    float4* out = (float4*)d_out;

    float4 *h0; uint2 *act, *act2; int2* srcw; int *off, *cur, *deg;
    cudaGetSymbolAddress((void**)&h0,   g_h0);
    cudaGetSymbolAddress((void**)&act,  g_act);
    cudaGetSymbolAddress((void**)&act2, g_act2);
    cudaGetSymbolAddress((void**)&srcw, g_srcw);
    cudaGetSymbolAddress((void**)&off,  g_off);
    cudaGetSymbolAddress((void**)&cur,  g_cur);
    cudaGetSymbolAddress((void**)&deg,  g_deg);
    unsigned* state = (unsigned*)(deg + NMAX);

    const int nb = (n + CHUNK - 1) / CHUNK;

    cudaLaunchAttribute pa[1];
    pa[0].id = cudaLaunchAttributeProgrammaticStreamSerialization;
    pa[0].val.programmaticStreamSerializationAllowed = 1;

    cudaLaunchConfig_t cfg{};
    cfg.blockDim = dim3(256);
    cfg.dynamicSmemBytes = 0;
    cfg.stream = 0;
    cfg.attrs = pa;
    cfg.numAttrs = 1;

    // 0. Zero deg + lookback state (one memset)
    cudaMemsetAsync(deg, 0, (size_t)(NMAX + NBLK) * sizeof(int), 0);

    // 1. CSR build chain (PDL)
    cfg.gridDim = dim3((E / 4 + 255) / 256);
    cudaLaunchKernelEx(&cfg, hist_kernel, ei + E, deg, E);

    cfg.gridDim = dim3(nb);
    cudaLaunchKernelEx(&cfg, scan_kernel, (const int*)deg, state, off, cur, n, nb);

    cfg.gridDim = dim3((E / 4 + 255) / 256);
    cudaLaunchKernelEx(&cfg, fill_kernel, ei, ei + E, ef, cur, srcw, E);

    // 2. Tensor-core Linear + LN0 + ReLU — PDL, independent of CSR build.
    const int gemm_blocks = (n + 127) / 128;
    const int gemm_smem = 2 * 128 * GLDA * (int)sizeof(half);   // 69632 B
    cudaFuncSetAttribute(gemm_ln_kernel,
                         cudaFuncAttributeMaxDynamicSharedMemorySize, gemm_smem);
    cfg.gridDim = dim3(gemm_blocks);
    cfg.blockDim = dim3(512);
    cfg.dynamicSmemBytes = gemm_smem;
    cudaLaunchKernelEx(&cfg, gemm_ln_kernel, x, W, b, lns, lnb,
                       (float*)h0, (unsigned*)act, n);
    cfg.blockDim = dim3(256);
    cfg.dynamicSmemBytes = 0;

    // 3. Layer 0 aggregation + residual + LN1 + ReLU — plain launch (full
    //    barrier: needs gemm + CSR complete).
    const int spmm_blocks = (n + 7) / 8;
    spmm_csr_kernel<true, false><<<spmm_blocks, 256>>>(off, srcw, act, h0,
                                                       lns + HID, lnb + HID,
                                                       act2, nullptr, n);

    // 4. Layer 1 aggregation -> final fp32 output — PDL prefetch of off/srcw.
    cfg.gridDim = dim3(spmm_blocks);
    cudaLaunchKernelEx(&cfg, spmm_csr_kernel<false, true>,
                       (const int*)off, (const int2*)srcw, (const uint2*)act2,
                       (const float4*)nullptr, (const float*)nullptr,
                       (const float*)nullptr, (uint2*)nullptr, out, n);
}

// round 15
// speedup vs baseline: 1.6358x; 1.0753x over previous
#include <cuda_runtime.h>
#include <cuda_fp16.h>
#include <cstdint>

#define NMAX 100000
#define EMAX 1600000
#define HID 128
#define EPS 1e-5f
#define CHUNK 1024
#define NBLK ((NMAX + CHUNK - 1) / CHUNK)   // 98
#define GLDA 136    // smem row stride in halfs: 272B = 17 x 16B -> ldmatrix conflict-free

#define FLAG_PART 0x40000000u
#define FLAG_DONE 0x80000000u
#define VAL_MASK  0x3FFFFFFFu

// Scratch (no cudaMalloc allowed).
__device__ float4 g_h0  [(size_t)NMAX * HID / 4];  // post-linear ("ori"), fp32
__device__ uint2  g_act [(size_t)NMAX * HID / 4];  // layer-0 input, fp16
__device__ uint2  g_act2[(size_t)NMAX * HID / 4];  // layer-1 input, fp16
__device__ int2   g_srcw[EMAX];                    // CSR payload: (src, w-bits)
__device__ int    g_off [NMAX + 1];
__device__ int    g_cur [NMAX];
__device__ int    g_deg [NMAX + NBLK];             // deg + lookback state (one memset)

__device__ __forceinline__ unsigned pack_h2(float a, float b)
{
    half2 h = __floats2half2_rn(a, b);
    return *(unsigned*)&h;
}

__device__ __forceinline__ uint2 pack_h4(float a, float b, float c, float d)
{
    return make_uint2(pack_h2(a, b), pack_h2(c, d));
}

__device__ __forceinline__ uint32_t s2u(const void* p)
{
    uint32_t a;
    asm("{ .reg .u64 t; cvta.to.shared.u64 t, %1; cvt.u32.u64 %0, t; }"
        : "=r"(a) : "l"(p));
    return a;
}

__device__ __forceinline__ void ldm_x4(uint32_t* r, uint32_t addr)
{
    asm volatile("ldmatrix.sync.aligned.m8n8.x4.shared.b16 {%0,%1,%2,%3}, [%4];"
                 : "=r"(r[0]), "=r"(r[1]), "=r"(r[2]), "=r"(r[3]) : "r"(addr));
}

__device__ __forceinline__ void mma16816(float* c, const uint32_t* a, const uint32_t* b)
{
    asm volatile("mma.sync.aligned.m16n8k16.row.col.f32.f16.f16.f32 "
                 "{%0,%1,%2,%3}, {%4,%5,%6,%7}, {%8,%9}, {%0,%1,%2,%3};"
                 : "+f"(c[0]), "+f"(c[1]), "+f"(c[2]), "+f"(c[3])
                 : "r"(a[0]), "r"(a[1]), "r"(a[2]), "r"(a[3]),
                   "r"(b[0]), "r"(b[1]));
}

// ---------------------------------------------------------------------------
// Tensor-core GEMM (fp16 in, fp32 accum) + bias + fused LN0 + ReLU epilogue.
// 512 threads / 16 warps; block tile 128x128; warp tile 16 rows x 64 cols.
// Runs on a forked stream, fully concurrent with the CSR build chain.
// ---------------------------------------------------------------------------
extern __shared__ char smem_raw[];
__global__ void __launch_bounds__(512)
gemm_ln_kernel(const float* __restrict__ x,
               const float* __restrict__ W,
               const float* __restrict__ b,
               const float* __restrict__ lns,
               const float* __restrict__ lnb,
               float* __restrict__ h0,
               unsigned* __restrict__ act,
               int n)
{
    half* ws = (half*)smem_raw;               // [128][GLDA] fp16 W
    half* xs = ws + 128 * GLDA;               // [128][GLDA] fp16 x tile
    const int tid  = threadIdx.x;
    const int lane = tid & 31;
    const int warp = tid >> 5;                // 0..15
    const int wr   = warp >> 1;               // row group 0..7
    const int cg   = warp & 1;                // col group 0..1
    const int row0 = blockIdx.x * 128;

    for (int idx = tid; idx < HID * HID; idx += 512) {
        int j = idx >> 7, k = idx & 127;
        ws[j * GLDA + k] = __float2half(W[idx]);
    }
    for (int idx = tid; idx < 128 * HID; idx += 512) {
        int r = idx >> 7, k = idx & 127;
        int row = row0 + r;
        xs[r * GLDA + k] = (row < n) ? __float2half(x[(size_t)row * HID + k])
                                     : __half(0.f);
    }
    __syncthreads();

    const uint32_t xs_u = s2u(xs);
    const uint32_t ws_u = s2u(ws);

    float c[8][4];
    #pragma unroll
    for (int t = 0; t < 8; t++)
        #pragma unroll
        for (int i = 0; i < 4; i++) c[t][i] = 0.f;

    const uint32_t a_base = xs_u +
        (uint32_t)(((wr * 16 + (lane & 15)) * GLDA + ((lane >> 4) << 3)) * 2);
    const uint32_t b_base = ws_u +
        (uint32_t)(((cg * 64 + ((lane >> 4) << 3) + (lane & 7)) * GLDA +
                    (((lane >> 3) & 1) << 3)) * 2);

    #pragma unroll
    for (int ks = 0; ks < 8; ks++) {
        const uint32_t koff = ks * 16 * 2;    // bytes
        uint32_t a[4];
        ldm_x4(a, a_base + koff);
        uint32_t bf[4][4];
        #pragma unroll
        for (int tp = 0; tp < 4; tp++)
            ldm_x4(bf[tp], b_base + (uint32_t)(tp * 16 * GLDA * 2) + koff);
        #pragma unroll
        for (int tp = 0; tp < 4; tp++) {
            mma16816(c[2 * tp + 0], a, &bf[tp][0]);
            mma16816(c[2 * tp + 1], a, &bf[tp][2]);
        }
    }

    #pragma unroll
    for (int t = 0; t < 8; t++) {
        float2 bb = __ldg((const float2*)&b[cg * 64 + t * 8 + (lane & 3) * 2]);
        c[t][0] += bb.x; c[t][1] += bb.y;
        c[t][2] += bb.x; c[t][3] += bb.y;
    }

    // Row moments over this warp's 64 cols
    float s_lo = 0.f, s_hi = 0.f, q_lo = 0.f, q_hi = 0.f;
    #pragma unroll
    for (int t = 0; t < 8; t++) {
        s_lo += c[t][0] + c[t][1];
        s_hi += c[t][2] + c[t][3];
        q_lo += c[t][0] * c[t][0] + c[t][1] * c[t][1];
        q_hi += c[t][2] * c[t][2] + c[t][3] * c[t][3];
    }
    #pragma unroll
    for (int o = 1; o <= 2; o <<= 1) {
        s_lo += __shfl_xor_sync(0xffffffffu, s_lo, o);
        s_hi += __shfl_xor_sync(0xffffffffu, s_hi, o);
        q_lo += __shfl_xor_sync(0xffffffffu, q_lo, o);
        q_hi += __shfl_xor_sync(0xffffffffu, q_hi, o);
    }

    float2* red = (float2*)smem_raw;          // [128][2], reuse staging smem
    __syncthreads();
    const int lrow_lo = wr * 16 + (lane >> 2);
    if ((lane & 3) == 0) {
        red[lrow_lo * 2 + cg]       = make_float2(s_lo, q_lo);
        red[(lrow_lo + 8) * 2 + cg] = make_float2(s_hi, q_hi);
    }
    __syncthreads();
    float2 m0 = red[lrow_lo * 2 + 0],       m1 = red[lrow_lo * 2 + 1];
    float2 n0 = red[(lrow_lo + 8) * 2 + 0], n1 = red[(lrow_lo + 8) * 2 + 1];
    const float mu_lo   = (m0.x + m1.x) * (1.f / HID);
    const float mu_hi   = (n0.x + n1.x) * (1.f / HID);
    const float rstd_lo = rsqrtf(fmaxf((m0.y + m1.y) * (1.f / HID) - mu_lo * mu_lo, 0.f) + EPS);
    const float rstd_hi = rsqrtf(fmaxf((n0.y + n1.y) * (1.f / HID) - mu_hi * mu_hi, 0.f) + EPS);

    const int row_lo = row0 + lrow_lo;
    const int row_hi = row_lo + 8;
    const bool v_lo = (row_lo < n), v_hi = (row_hi < n);
    #pragma unroll
    for (int t = 0; t < 8; t++) {
        const int colp = cg * 64 + t * 8 + (lane & 3) * 2;
        float2 sc = __ldg((const float2*)&lns[colp]);
        float2 bi = __ldg((const float2*)&lnb[colp]);
        if (v_lo) {
            *(float2*)&h0[(size_t)row_lo * HID + colp] = make_float2(c[t][0], c[t][1]);
            act[(size_t)row_lo * 64 + (colp >> 1)] = pack_h2(
                fmaxf((c[t][0] - mu_lo) * rstd_lo * sc.x + bi.x, 0.f),
                fmaxf((c[t][1] - mu_lo) * rstd_lo * sc.y + bi.y, 0.f));
        }
        if (v_hi) {
            *(float2*)&h0[(size_t)row_hi * HID + colp] = make_float2(c[t][2], c[t][3]);
            act[(size_t)row_hi * 64 + (colp >> 1)] = pack_h2(
                fmaxf((c[t][2] - mu_hi) * rstd_hi * sc.x + bi.x, 0.f),
                fmaxf((c[t][3] - mu_hi) * rstd_hi * sc.y + bi.y, 0.f));
        }
    }
}

// ---------------------------------------------------------------------------
// CSR build.  hist: PDL — load input quad, sync on memset, then atomics.
// ---------------------------------------------------------------------------
__global__ void hist_kernel(const int* __restrict__ dst, int* __restrict__ deg, int E)
{
    int e0 = (blockIdx.x * blockDim.x + threadIdx.x) * 4;
    if (e0 + 3 < E) {
        int4 d = *(const int4*)&dst[e0];
        cudaGridDependencySynchronize();
        atomicAdd(&deg[d.x], 1); atomicAdd(&deg[d.y], 1);
        atomicAdd(&deg[d.z], 1); atomicAdd(&deg[d.w], 1);
    } else {
        cudaGridDependencySynchronize();
        for (int e = e0; e < E; e++) atomicAdd(&deg[dst[e]], 1);
    }
}

// Single-pass exclusive scan of deg -> off/cur via decoupled lookback.
__global__ void scan_kernel(const int* __restrict__ deg,
                            unsigned* __restrict__ state,
                            int* __restrict__ off,
                            int* __restrict__ cur, int n, int nb)
{
    cudaGridDependencySynchronize();          // wait for hist (PDL launch)
    __shared__ int sh[256];
    __shared__ int s_base;
    const int t   = threadIdx.x;
    const int bid = blockIdx.x;
    const int base = bid * CHUNK + t * 4;

    int d[4];
    #pragma unroll
    for (int j = 0; j < 4; j++)
        d[j] = (base + j < n) ? deg[base + j] : 0;
    int local = d[0] + d[1] + d[2] + d[3];

    sh[t] = local;
    __syncthreads();
    for (int o = 1; o < 256; o <<= 1) {       // inclusive Hillis-Steele
        int u = (t >= o) ? sh[t - o] : 0;
        __syncthreads();
        sh[t] += u;
        __syncthreads();
    }

    if (t == 0) {
        unsigned agg = (unsigned)sh[255];
        int run = 0;
        if (bid == 0) {
            atomicExch(&state[0], agg | FLAG_DONE);
        } else {
            atomicExch(&state[bid], agg | FLAG_PART);
            int p = bid - 1;
            for (;;) {
                unsigned s;
                do { s = atomicAdd(&state[p], 0u); } while (s == 0u);
                run += (int)(s & VAL_MASK);
                if (s & FLAG_DONE) break;
                p--;
            }
            atomicExch(&state[bid], ((unsigned)run + agg) | FLAG_DONE);
        }
        s_base = run;
        if (bid == nb - 1) off[n] = run + (int)agg;
    }
    __syncthreads();

    int run = s_base + sh[t] - local;         // exclusive base for elem 0
    #pragma unroll
    for (int j = 0; j < 4; j++) {
        int i = base + j;
        if (i < n) { off[i] = run; cur[i] = run; run += d[j]; }
    }
}

__global__ void fill_kernel(const int* __restrict__ src, const int* __restrict__ dst,
                            const float* __restrict__ ef,
                            int* __restrict__ cur, int2* __restrict__ srcw, int E)
{
    int e0 = (blockIdx.x * blockDim.x + threadIdx.x) * 4;
    if (e0 + 3 < E) {
        int4   s = *(const int4*)&src[e0];
        int4   d = *(const int4*)&dst[e0];
        float4 w = *(const float4*)&ef[e0];
        cudaGridDependencySynchronize();       // wait scan (cur ready)
        int p0 = atomicAdd(&cur[d.x], 1);
        int p1 = atomicAdd(&cur[d.y], 1);
        int p2 = atomicAdd(&cur[d.z], 1);
        int p3 = atomicAdd(&cur[d.w], 1);
        srcw[p0] = make_int2(s.x, __float_as_int(w.x));
        srcw[p1] = make_int2(s.y, __float_as_int(w.y));
        srcw[p2] = make_int2(s.z, __float_as_int(w.z));
        srcw[p3] = make_int2(s.w, __float_as_int(w.w));
    } else {
        cudaGridDependencySynchronize();
        for (int e = e0; e < E; e++) {
            int p = atomicAdd(&cur[dst[e]], 1);
            srcw[p] = make_int2(src[e], __float_as_int(ef[e]));
        }
    }
}

// ---------------------------------------------------------------------------
// SpMM gather-reduce over fp16 features, fp32 accumulation.
// MODE 0: plain.  MODE 1: PDL, prefetch off only (srcw not yet stable).
// MODE 2: PDL, prefetch off + first srcw batch (both stable).
// ---------------------------------------------------------------------------
template <bool FUSE_LN, int MODE>
__global__ void spmm_csr_kernel(const int* __restrict__ off,
                                const int2* __restrict__ srcw,
                                const uint2* __restrict__ hin,
                                const float4* __restrict__ h0,
                                const float* __restrict__ lns,
                                const float* __restrict__ lnb,
                                uint2* __restrict__ out_h,
                                float4* __restrict__ out_f, int n)
{
    const int node = blockIdx.x * 8 + (threadIdx.x >> 5);
    const int lane = threadIdx.x & 31;
    if (node >= n) {
        if (MODE != 0) cudaGridDependencySynchronize();
        return;
    }

    const int beg = off[node];
    const int end = off[node + 1];

    int cnt = min(end - beg, 32);
    int2 sw = make_int2(0, 0);
    if (MODE == 2) {
        if (lane < cnt) sw = __ldg(&srcw[beg + lane]);
    }
    if (MODE != 0) cudaGridDependencySynchronize();
    if (MODE != 2) {
        if (lane < cnt) sw = __ldg(&srcw[beg + lane]);
    }

    float4 a = make_float4(0.f, 0.f, 0.f, 0.f);
    for (int base = beg; base < end; base += 32) {
        #pragma unroll 8
        for (int j = 0; j < cnt; j++) {
            int   s = __shfl_sync(0xffffffffu, sw.x, j);
            float w = __int_as_float(__shfl_sync(0xffffffffu, sw.y, j));
            uint2 p = __ldg(&hin[(size_t)s * 32 + lane]);
            float2 lo = __half22float2(*(half2*)&p.x);
            float2 hi = __half22float2(*(half2*)&p.y);
            a.x += lo.x * w; a.y += lo.y * w;
            a.z += hi.x * w; a.w += hi.y * w;
        }
        int nb2 = base + 32;
        if (nb2 < end) {
            cnt = min(end - nb2, 32);
            sw = make_int2(0, 0);
            if (lane < cnt) sw = __ldg(&srcw[nb2 + lane]);
        }
    }

    if (FUSE_LN) {
        float4 r = __ldg(&h0[(size_t)node * 32 + lane]);
        a.x += r.x; a.y += r.y; a.z += r.z; a.w += r.w;

        float s = a.x + a.y + a.z + a.w;
        #pragma unroll
        for (int o = 16; o > 0; o >>= 1) s += __shfl_xor_sync(0xffffffffu, s, o);
        float mu = s * (1.f / HID);
        float dx = a.x - mu, dy = a.y - mu, dz = a.z - mu, dw = a.w - mu;
        float q = dx * dx + dy * dy + dz * dz + dw * dw;
        #pragma unroll
        for (int o = 16; o > 0; o >>= 1) q += __shfl_xor_sync(0xffffffffu, q, o);
        float rstd = rsqrtf(q * (1.f / HID) + EPS);

        int j0 = lane * 4;
        float4 sc = __ldg((const float4*)&lns[j0]);
        float4 bi = __ldg((const float4*)&lnb[j0]);
        out_h[(size_t)node * 32 + lane] = pack_h4(
            fmaxf(dx * rstd * sc.x + bi.x, 0.f),
            fmaxf(dy * rstd * sc.y + bi.y, 0.f),
            fmaxf(dz * rstd * sc.z + bi.z, 0.f),
            fmaxf(dw * rstd * sc.w + bi.w, 0.f));
    } else {
        out_f[(size_t)node * 32 + lane] = a;
    }
}

// ---------------------------------------------------------------------------
extern "C" void kernel_launch(void* const* d_in, const int* in_sizes, int n_in,
                              void* d_out, int out_size)
{
    const float* x   = (const float*)d_in[0];
    const int*   ei  = (const int*)d_in[1];     // [2, E] int32
    const float* ef  = (const float*)d_in[2];
    const float* W   = (const float*)d_in[3];
    const float* b   = (const float*)d_in[4];
    const float* lns = (const float*)d_in[5];
    const float* lnb = (const float*)d_in[6];

    const int n = in_sizes[0] / HID;
    const int E = in_sizes[2];
    float4* out = (float4*)d_out;

    float4 *h0; uint2 *act, *act2; int2* srcw; int *off, *cur, *deg;
    cudaGetSymbolAddress((void**)&h0,   g_h0);
    cudaGetSymbolAddress((void**)&act,  g_act);
    cudaGetSymbolAddress((void**)&act2, g_act2);
    cudaGetSymbolAddress((void**)&srcw, g_srcw);
    cudaGetSymbolAddress((void**)&off,  g_off);
    cudaGetSymbolAddress((void**)&cur,  g_cur);
    cudaGetSymbolAddress((void**)&deg,  g_deg);
    unsigned* state = (unsigned*)(deg + NMAX);

    const int nb = (n + CHUNK - 1) / CHUNK;

    // Fork resources (host-side only; kernel_launch runs a handful of times —
    // correctness + capture — so not destroying them is a trivial host leak,
    // and destroying mid-capture would be illegal).
    cudaStream_t s2 = 0;
    cudaEvent_t evFork = 0, evJoin = 0;
    bool forked =
        (cudaStreamCreateWithFlags(&s2, cudaStreamNonBlocking) == cudaSuccess) &&
        (cudaEventCreateWithFlags(&evFork, cudaEventDisableTiming) == cudaSuccess) &&
        (cudaEventCreateWithFlags(&evJoin, cudaEventDisableTiming) == cudaSuccess);

    cudaLaunchAttribute pa[1];
    pa[0].id = cudaLaunchAttributeProgrammaticStreamSerialization;
    pa[0].val.programmaticStreamSerializationAllowed = 1;

    cudaLaunchConfig_t cfg{};
    cfg.blockDim = dim3(256);
    cfg.dynamicSmemBytes = 0;
    cfg.stream = 0;
    cfg.attrs = pa;
    cfg.numAttrs = 1;

    // Fork: gemm on s2, concurrent with the whole CSR chain on stream 0.
    const int gemm_blocks = (n + 127) / 128;
    const int gemm_smem = 2 * 128 * GLDA * (int)sizeof(half);   // 69632 B
    cudaFuncSetAttribute(gemm_ln_kernel,
                         cudaFuncAttributeMaxDynamicSharedMemorySize, gemm_smem);
    if (forked) {
        cudaEventRecord(evFork, 0);
        cudaStreamWaitEvent(s2, evFork, 0);
        gemm_ln_kernel<<<gemm_blocks, 512, gemm_smem, s2>>>(
            x, W, b, lns, lnb, (float*)h0, (unsigned*)act, n);
        cudaEventRecord(evJoin, s2);
    }

    // Stream 0: CSR build chain (PDL within the chain).
    cudaMemsetAsync(deg, 0, (size_t)(NMAX + NBLK) * sizeof(int), 0);

    cfg.gridDim = dim3((E / 4 + 255) / 256);
    cudaLaunchKernelEx(&cfg, hist_kernel, ei + E, deg, E);

    cfg.gridDim = dim3(nb);
    cudaLaunchKernelEx(&cfg, scan_kernel, (const int*)deg, state, off, cur, n, nb);

    cfg.gridDim = dim3((E / 4 + 255) / 256);
    cudaLaunchKernelEx(&cfg, fill_kernel, ei, ei + E, ef, cur, srcw, E);

    if (forked) {
        cudaStreamWaitEvent(0, evJoin, 0);    // join gemm before spmm0
    } else {
        // Fallback: serial gemm on stream 0 (previous behavior)
        gemm_ln_kernel<<<gemm_blocks, 512, gemm_smem, 0>>>(
            x, W, b, lns, lnb, (float*)h0, (unsigned*)act, n);
    }

    // Layer 0 aggregation + residual + LN1 + ReLU.  PDL MODE 1: prefetch off
    // (stable after scan; fill/gemm don't write it), sync, then read srcw.
    const int spmm_blocks = (n + 7) / 8;
    cfg.gridDim = dim3(spmm_blocks);
    cudaLaunchKernelEx(&cfg, spmm_csr_kernel<true, 1>,
                       (const int*)off, (const int2*)srcw, (const uint2*)act,
                       (const float4*)h0, (const float*)(lns + HID),
                       (const float*)(lnb + HID), act2, (float4*)nullptr, n);

    // Layer 1 aggregation -> final fp32 output.  PDL MODE 2: prefetch
    // off + srcw (stable since before spmm0).
    cudaLaunchKernelEx(&cfg, spmm_csr_kernel<false, 2>,
                       (const int*)off, (const int2*)srcw, (const uint2*)act2,
                       (const float4*)nullptr, (const float*)nullptr,
                       (const float*)nullptr, (uint2*)nullptr, out, n);
}

// round 16
// speedup vs baseline: 1.7309x; 1.0581x over previous
#include <cuda_runtime.h>
#include <cuda_fp16.h>
#include <cstdint>

#define NMAX 100000
#define EMAX 1600000
#define HID 128
#define EPS 1e-5f
#define CHUNK 1024
#define NBLK ((NMAX + CHUNK - 1) / CHUNK)   // 98
#define GLDA 136    // smem row stride in halfs: 272B = 17 x 16B -> ldmatrix conflict-free

#define FLAG_PART 0x40000000u
#define FLAG_DONE 0x80000000u
#define VAL_MASK  0x3FFFFFFFu

// Scratch (no cudaMalloc allowed).
__device__ uint2  g_h0  [(size_t)NMAX * HID / 4];  // post-linear ("ori"), fp16
__device__ uint2  g_act [(size_t)NMAX * HID / 4];  // layer-0 input, fp16
__device__ uint2  g_act2[(size_t)NMAX * HID / 4];  // layer-1 input, fp16
__device__ half   g_w16 [HID * HID];               // W converted to fp16 (once)
__device__ int2   g_srcw[EMAX];                    // CSR payload: (src, w-bits)
__device__ int    g_off [NMAX + 1];
__device__ int    g_cur [NMAX];
__device__ int    g_deg [NMAX + NBLK];             // deg + lookback state (one memset)

__device__ __forceinline__ unsigned pack_h2(float a, float b)
{
    half2 h = __floats2half2_rn(a, b);
    return *(unsigned*)&h;
}

__device__ __forceinline__ uint2 pack_h4(float a, float b, float c, float d)
{
    return make_uint2(pack_h2(a, b), pack_h2(c, d));
}

__device__ __forceinline__ uint32_t s2u(const void* p)
{
    uint32_t a;
    asm("{ .reg .u64 t; cvta.to.shared.u64 t, %1; cvt.u32.u64 %0, t; }"
        : "=r"(a) : "l"(p));
    return a;
}

__device__ __forceinline__ void ldm_x4(uint32_t* r, uint32_t addr)
{
    asm volatile("ldmatrix.sync.aligned.m8n8.x4.shared.b16 {%0,%1,%2,%3}, [%4];"
                 : "=r"(r[0]), "=r"(r[1]), "=r"(r[2]), "=r"(r[3]) : "r"(addr));
}

__device__ __forceinline__ void mma16816(float* c, const uint32_t* a, const uint32_t* b)
{
    asm volatile("mma.sync.aligned.m16n8k16.row.col.f32.f16.f16.f32 "
                 "{%0,%1,%2,%3}, {%4,%5,%6,%7}, {%8,%9}, {%0,%1,%2,%3};"
                 : "+f"(c[0]), "+f"(c[1]), "+f"(c[2]), "+f"(c[3])
                 : "r"(a[0]), "r"(a[1]), "r"(a[2]), "r"(a[3]),
                   "r"(b[0]), "r"(b[1]));
}

// ---------------------------------------------------------------------------
// One-shot W fp32 -> fp16 conversion (16 blocks x 256; ~2us, on fork stream).
// ---------------------------------------------------------------------------
__global__ void wcvt_kernel(const float* __restrict__ W, half* __restrict__ W16)
{
    int i = blockIdx.x * 256 + threadIdx.x;       // 4096 threads x float4
    float4 w = __ldg((const float4*)&W[i * 4]);
    *(uint2*)&W16[i * 4] = make_uint2(pack_h2(w.x, w.y), pack_h2(w.z, w.w));
}

// ---------------------------------------------------------------------------
// Tensor-core GEMM (fp16 in, fp32 accum) + bias + fused LN0 + ReLU epilogue.
// 512 threads / 16 warps; block tile 128x128; warp tile 16 rows x 64 cols.
// Staging fully vectorized: W via uint4 copies of precomputed fp16, x via
// float4 -> 2x half2.  Writes h0 (fp16 residual) and act (fp16 post-LN+ReLU).
// ---------------------------------------------------------------------------
extern __shared__ char smem_raw[];
__global__ void __launch_bounds__(512)
gemm_ln_kernel(const float* __restrict__ x,
               const half* __restrict__ W16,
               const float* __restrict__ b,
               const float* __restrict__ lns,
               const float* __restrict__ lnb,
               unsigned* __restrict__ h0,    // fp16 x2 per word
               unsigned* __restrict__ act,   // fp16 x2 per word
               int n)
{
    half* ws = (half*)smem_raw;               // [128][GLDA] fp16 W
    half* xs = ws + 128 * GLDA;               // [128][GLDA] fp16 x tile
    const int tid  = threadIdx.x;
    const int lane = tid & 31;
    const int warp = tid >> 5;                // 0..15
    const int wr   = warp >> 1;               // row group 0..7
    const int cg   = warp & 1;                // col group 0..1
    const int row0 = blockIdx.x * 128;

    // Stage W: 2048 uint4 (16B) copies
    const uint4* w16v = (const uint4*)W16;
    #pragma unroll
    for (int idx = tid; idx < 2048; idx += 512) {
        int j = idx >> 4, k16 = idx & 15;
        *(uint4*)&ws[j * GLDA + k16 * 8] = __ldg(&w16v[idx]);
    }
    // Stage x: 4096 float4 reads -> uint2 (8B) stores
    #pragma unroll
    for (int idx = tid; idx < 4096; idx += 512) {
        int r = idx >> 5, k4 = idx & 31;
        int row = row0 + r;
        uint2 p = make_uint2(0u, 0u);
        if (row < n) {
            float4 v = __ldg((const float4*)&x[(size_t)row * HID + k4 * 4]);
            p = make_uint2(pack_h2(v.x, v.y), pack_h2(v.z, v.w));
        }
        *(uint2*)&xs[r * GLDA + k4 * 4] = p;
    }
    __syncthreads();

    const uint32_t xs_u = s2u(xs);
    const uint32_t ws_u = s2u(ws);

    float c[8][4];
    #pragma unroll
    for (int t = 0; t < 8; t++)
        #pragma unroll
        for (int i = 0; i < 4; i++) c[t][i] = 0.f;

    const uint32_t a_base = xs_u +
        (uint32_t)(((wr * 16 + (lane & 15)) * GLDA + ((lane >> 4) << 3)) * 2);
    const uint32_t b_base = ws_u +
        (uint32_t)(((cg * 64 + ((lane >> 4) << 3) + (lane & 7)) * GLDA +
                    (((lane >> 3) & 1) << 3)) * 2);

    #pragma unroll
    for (int ks = 0; ks < 8; ks++) {
        const uint32_t koff = ks * 16 * 2;    // bytes
        uint32_t a[4];
        ldm_x4(a, a_base + koff);
        uint32_t bf[4][4];
        #pragma unroll
        for (int tp = 0; tp < 4; tp++)
            ldm_x4(bf[tp], b_base + (uint32_t)(tp * 16 * GLDA * 2) + koff);
        #pragma unroll
        for (int tp = 0; tp < 4; tp++) {
            mma16816(c[2 * tp + 0], a, &bf[tp][0]);
            mma16816(c[2 * tp + 1], a, &bf[tp][2]);
        }
    }

    #pragma unroll
    for (int t = 0; t < 8; t++) {
        float2 bb = __ldg((const float2*)&b[cg * 64 + t * 8 + (lane & 3) * 2]);
        c[t][0] += bb.x; c[t][1] += bb.y;
        c[t][2] += bb.x; c[t][3] += bb.y;
    }

    // Row moments over this warp's 64 cols
    float s_lo = 0.f, s_hi = 0.f, q_lo = 0.f, q_hi = 0.f;
    #pragma unroll
    for (int t = 0; t < 8; t++) {
        s_lo += c[t][0] + c[t][1];
        s_hi += c[t][2] + c[t][3];
        q_lo += c[t][0] * c[t][0] + c[t][1] * c[t][1];
        q_hi += c[t][2] * c[t][2] + c[t][3] * c[t][3];
    }
    #pragma unroll
    for (int o = 1; o <= 2; o <<= 1) {
        s_lo += __shfl_xor_sync(0xffffffffu, s_lo, o);
        s_hi += __shfl_xor_sync(0xffffffffu, s_hi, o);
        q_lo += __shfl_xor_sync(0xffffffffu, q_lo, o);
        q_hi += __shfl_xor_sync(0xffffffffu, q_hi, o);
    }

    float2* red = (float2*)smem_raw;          // [128][2], reuse staging smem
    __syncthreads();
    const int lrow_lo = wr * 16 + (lane >> 2);
    if ((lane & 3) == 0) {
        red[lrow_lo * 2 + cg]       = make_float2(s_lo, q_lo);
        red[(lrow_lo + 8) * 2 + cg] = make_float2(s_hi, q_hi);
    }
    __syncthreads();
    float2 m0 = red[lrow_lo * 2 + 0],       m1 = red[lrow_lo * 2 + 1];
    float2 n0 = red[(lrow_lo + 8) * 2 + 0], n1 = red[(lrow_lo + 8) * 2 + 1];
    const float mu_lo   = (m0.x + m1.x) * (1.f / HID);
    const float mu_hi   = (n0.x + n1.x) * (1.f / HID);
    const float rstd_lo = rsqrtf(fmaxf((m0.y + m1.y) * (1.f / HID) - mu_lo * mu_lo, 0.f) + EPS);
    const float rstd_hi = rsqrtf(fmaxf((n0.y + n1.y) * (1.f / HID) - mu_hi * mu_hi, 0.f) + EPS);

    const int row_lo = row0 + lrow_lo;
    const int row_hi = row_lo + 8;
    const bool v_lo = (row_lo < n), v_hi = (row_hi < n);
    #pragma unroll
    for (int t = 0; t < 8; t++) {
        const int colp = cg * 64 + t * 8 + (lane & 3) * 2;
        float2 sc = __ldg((const float2*)&lns[colp]);
        float2 bi = __ldg((const float2*)&lnb[colp]);
        if (v_lo) {
            h0[(size_t)row_lo * 64 + (colp >> 1)] = pack_h2(c[t][0], c[t][1]);
            act[(size_t)row_lo * 64 + (colp >> 1)] = pack_h2(
                fmaxf((c[t][0] - mu_lo) * rstd_lo * sc.x + bi.x, 0.f),
                fmaxf((c[t][1] - mu_lo) * rstd_lo * sc.y + bi.y, 0.f));
        }
        if (v_hi) {
            h0[(size_t)row_hi * 64 + (colp >> 1)] = pack_h2(c[t][2], c[t][3]);
            act[(size_t)row_hi * 64 + (colp >> 1)] = pack_h2(
                fmaxf((c[t][2] - mu_hi) * rstd_hi * sc.x + bi.x, 0.f),
                fmaxf((c[t][3] - mu_hi) * rstd_hi * sc.y + bi.y, 0.f));
        }
    }
}

// ---------------------------------------------------------------------------
// CSR build.  hist: PDL — load input quad, sync on memset, then atomics.
// ---------------------------------------------------------------------------
__global__ void hist_kernel(const int* __restrict__ dst, int* __restrict__ deg, int E)
{
    int e0 = (blockIdx.x * blockDim.x + threadIdx.x) * 4;
    if (e0 + 3 < E) {
        int4 d = *(const int4*)&dst[e0];
        cudaGridDependencySynchronize();
        atomicAdd(&deg[d.x], 1); atomicAdd(&deg[d.y], 1);
        atomicAdd(&deg[d.z], 1); atomicAdd(&deg[d.w], 1);
    } else {
        cudaGridDependencySynchronize();
        for (int e = e0; e < E; e++) atomicAdd(&deg[dst[e]], 1);
    }
}

// Single-pass exclusive scan of deg -> off/cur via decoupled lookback.
__global__ void scan_kernel(const int* __restrict__ deg,
                            unsigned* __restrict__ state,
                            int* __restrict__ off,
                            int* __restrict__ cur, int n, int nb)
{
    cudaGridDependencySynchronize();          // wait for hist (PDL launch)
    __shared__ int sh[256];
    __shared__ int s_base;
    const int t   = threadIdx.x;
    const int bid = blockIdx.x;
    const int base = bid * CHUNK + t * 4;

    int d[4];
    #pragma unroll
    for (int j = 0; j < 4; j++)
        d[j] = (base + j < n) ? deg[base + j] : 0;
    int local = d[0] + d[1] + d[2] + d[3];

    sh[t] = local;
    __syncthreads();
    for (int o = 1; o < 256; o <<= 1) {       // inclusive Hillis-Steele
        int u = (t >= o) ? sh[t - o] : 0;
        __syncthreads();
        sh[t] += u;
        __syncthreads();
    }

    if (t == 0) {
        unsigned agg = (unsigned)sh[255];
        int run = 0;
        if (bid == 0) {
            atomicExch(&state[0], agg | FLAG_DONE);
        } else {
            atomicExch(&state[bid], agg | FLAG_PART);
            int p = bid - 1;
            for (;;) {
                unsigned s;
                do { s = atomicAdd(&state[p], 0u); } while (s == 0u);
                run += (int)(s & VAL_MASK);
                if (s & FLAG_DONE) break;
                p--;
            }
            atomicExch(&state[bid], ((unsigned)run + agg) | FLAG_DONE);
        }
        s_base = run;
        if (bid == nb - 1) off[n] = run + (int)agg;
    }
    __syncthreads();

    int run = s_base + sh[t] - local;         // exclusive base for elem 0
    #pragma unroll
    for (int j = 0; j < 4; j++) {
        int i = base + j;
        if (i < n) { off[i] = run; cur[i] = run; run += d[j]; }
    }
}

__global__ void fill_kernel(const int* __restrict__ src, const int* __restrict__ dst,
                            const float* __restrict__ ef,
                            int* __restrict__ cur, int2* __restrict__ srcw, int E)
{
    int e0 = (blockIdx.x * blockDim.x + threadIdx.x) * 4;
    if (e0 + 3 < E) {
        int4   s = *(const int4*)&src[e0];
        int4   d = *(const int4*)&dst[e0];
        float4 w = *(const float4*)&ef[e0];
        cudaGridDependencySynchronize();       // wait scan (cur ready)
        int p0 = atomicAdd(&cur[d.x], 1);
        int p1 = atomicAdd(&cur[d.y], 1);
        int p2 = atomicAdd(&cur[d.z], 1);
        int p3 = atomicAdd(&cur[d.w], 1);
        srcw[p0] = make_int2(s.x, __float_as_int(w.x));
        srcw[p1] = make_int2(s.y, __float_as_int(w.y));
        srcw[p2] = make_int2(s.z, __float_as_int(w.z));
        srcw[p3] = make_int2(s.w, __float_as_int(w.w));
    } else {
        cudaGridDependencySynchronize();
        for (int e = e0; e < E; e++) {
            int p = atomicAdd(&cur[dst[e]], 1);
            srcw[p] = make_int2(src[e], __float_as_int(ef[e]));
        }
    }
}

// ---------------------------------------------------------------------------
// SpMM gather-reduce over fp16 features, fp32 accumulation.
// MODE 0: plain.  MODE 1: PDL, prefetch off only.  MODE 2: PDL, prefetch
// off + first srcw batch.
// FUSE_LN residual h16 is fp16 (uint2 = 4 cols per lane).
// ---------------------------------------------------------------------------
template <bool FUSE_LN, int MODE>
__global__ void spmm_csr_kernel(const int* __restrict__ off,
                                const int2* __restrict__ srcw,
                                const uint2* __restrict__ hin,
                                const uint2* __restrict__ h16,
                                const float* __restrict__ lns,
                                const float* __restrict__ lnb,
                                uint2* __restrict__ out_h,
                                float4* __restrict__ out_f, int n)
{
    const int node = blockIdx.x * 8 + (threadIdx.x >> 5);
    const int lane = threadIdx.x & 31;
    if (node >= n) {
        if (MODE != 0) cudaGridDependencySynchronize();
        return;
    }

    const int beg = off[node];
    const int end = off[node + 1];

    int cnt = min(end - beg, 32);
    int2 sw = make_int2(0, 0);
    if (MODE == 2) {
        if (lane < cnt) sw = __ldg(&srcw[beg + lane]);
    }
    if (MODE != 0) cudaGridDependencySynchronize();
    if (MODE != 2) {
        if (lane < cnt) sw = __ldg(&srcw[beg + lane]);
    }

    float4 a = make_float4(0.f, 0.f, 0.f, 0.f);
    for (int base = beg; base < end; base += 32) {
        #pragma unroll 8
        for (int j = 0; j < cnt; j++) {
            int   s = __shfl_sync(0xffffffffu, sw.x, j);
            float w = __int_as_float(__shfl_sync(0xffffffffu, sw.y, j));
            uint2 p = __ldg(&hin[(size_t)s * 32 + lane]);
            float2 lo = __half22float2(*(half2*)&p.x);
            float2 hi = __half22float2(*(half2*)&p.y);
            a.x += lo.x * w; a.y += lo.y * w;
            a.z += hi.x * w; a.w += hi.y * w;
        }
        int nb2 = base + 32;
        if (nb2 < end) {
            cnt = min(end - nb2, 32);
            sw = make_int2(0, 0);
            if (lane < cnt) sw = __ldg(&srcw[nb2 + lane]);
        }
    }

    if (FUSE_LN) {
        uint2 rp = __ldg(&h16[(size_t)node * 32 + lane]);
        float2 rlo = __half22float2(*(half2*)&rp.x);
        float2 rhi = __half22float2(*(half2*)&rp.y);
        a.x += rlo.x; a.y += rlo.y; a.z += rhi.x; a.w += rhi.y;

        float s = a.x + a.y + a.z + a.w;
        #pragma unroll
        for (int o = 16; o > 0; o >>= 1) s += __shfl_xor_sync(0xffffffffu, s, o);
        float mu = s * (1.f / HID);
        float dx = a.x - mu, dy = a.y - mu, dz = a.z - mu, dw = a.w - mu;
        float q = dx * dx + dy * dy + dz * dz + dw * dw;
        #pragma unroll
        for (int o = 16; o > 0; o >>= 1) q += __shfl_xor_sync(0xffffffffu, q, o);
        float rstd = rsqrtf(q * (1.f / HID) + EPS);

        int j0 = lane * 4;
        float4 sc = __ldg((const float4*)&lns[j0]);
        float4 bi = __ldg((const float4*)&lnb[j0]);
        out_h[(size_t)node * 32 + lane] = pack_h4(
            fmaxf(dx * rstd * sc.x + bi.x, 0.f),
            fmaxf(dy * rstd * sc.y + bi.y, 0.f),
            fmaxf(dz * rstd * sc.z + bi.z, 0.f),
            fmaxf(dw * rstd * sc.w + bi.w, 0.f));
    } else {
        out_f[(size_t)node * 32 + lane] = a;
    }
}

// ---------------------------------------------------------------------------
extern "C" void kernel_launch(void* const* d_in, const int* in_sizes, int n_in,
                              void* d_out, int out_size)
{
    const float* x   = (const float*)d_in[0];
    const int*   ei  = (const int*)d_in[1];     // [2, E] int32
    const float* ef  = (const float*)d_in[2];
    const float* W   = (const float*)d_in[3];
    const float* b   = (const float*)d_in[4];
    const float* lns = (const float*)d_in[5];
    const float* lnb = (const float*)d_in[6];

    const int n = in_sizes[0] / HID;
    const int E = in_sizes[2];
    float4* out = (float4*)d_out;

    uint2 *h0, *act, *act2; half* w16; int2* srcw; int *off, *cur, *deg;
    cudaGetSymbolAddress((void**)&h0,   g_h0);
    cudaGetSymbolAddress((void**)&act,  g_act);
    cudaGetSymbolAddress((void**)&act2, g_act2);
    cudaGetSymbolAddress((void**)&w16,  g_w16);
    cudaGetSymbolAddress((void**)&srcw, g_srcw);
    cudaGetSymbolAddress((void**)&off,  g_off);
    cudaGetSymbolAddress((void**)&cur,  g_cur);
    cudaGetSymbolAddress((void**)&deg,  g_deg);
    unsigned* state = (unsigned*)(deg + NMAX);

    const int nb = (n + CHUNK - 1) / CHUNK;

    // Fork resources (host-side only; created per call, never destroyed —
    // kernel_launch runs a handful of times, destroying mid-capture is illegal).
    cudaStream_t s2 = 0;
    cudaEvent_t evFork = 0, evJoin = 0;
    bool forked =
        (cudaStreamCreateWithFlags(&s2, cudaStreamNonBlocking) == cudaSuccess) &&
        (cudaEventCreateWithFlags(&evFork, cudaEventDisableTiming) == cudaSuccess) &&
        (cudaEventCreateWithFlags(&evJoin, cudaEventDisableTiming) == cudaSuccess);

    cudaLaunchAttribute pa[1];
    pa[0].id = cudaLaunchAttributeProgrammaticStreamSerialization;
    pa[0].val.programmaticStreamSerializationAllowed = 1;

    cudaLaunchConfig_t cfg{};
    cfg.blockDim = dim3(256);
    cfg.dynamicSmemBytes = 0;
    cfg.stream = 0;
    cfg.attrs = pa;
    cfg.numAttrs = 1;

    // Fork: wcvt + gemm on s2, concurrent with the CSR chain on stream 0.
    const int gemm_blocks = (n + 127) / 128;
    const int gemm_smem = 2 * 128 * GLDA * (int)sizeof(half);   // 69632 B
    cudaFuncSetAttribute(gemm_ln_kernel,
                         cudaFuncAttributeMaxDynamicSharedMemorySize, gemm_smem);
    if (forked) {
        cudaEventRecord(evFork, 0);
        cudaStreamWaitEvent(s2, evFork, 0);
        wcvt_kernel<<<16, 256, 0, s2>>>(W, w16);
        gemm_ln_kernel<<<gemm_blocks, 512, gemm_smem, s2>>>(
            x, w16, b, lns, lnb, (unsigned*)h0, (unsigned*)act, n);
        cudaEventRecord(evJoin, s2);
    }

    // Stream 0: CSR build chain (PDL within the chain).
    cudaMemsetAsync(deg, 0, (size_t)(NMAX + NBLK) * sizeof(int), 0);

    cfg.gridDim = dim3((E / 4 + 255) / 256);
    cudaLaunchKernelEx(&cfg, hist_kernel, ei + E, deg, E);

    cfg.gridDim = dim3(nb);
    cudaLaunchKernelEx(&cfg, scan_kernel, (const int*)deg, state, off, cur, n, nb);

    cfg.gridDim = dim3((E / 4 + 255) / 256);
    cudaLaunchKernelEx(&cfg, fill_kernel, ei, ei + E, ef, cur, srcw, E);

    if (forked) {
        cudaStreamWaitEvent(0, evJoin, 0);    // join gemm before spmm0
    } else {
        wcvt_kernel<<<16, 256>>>(W, w16);
        gemm_ln_kernel<<<gemm_blocks, 512, gemm_smem, 0>>>(
            x, w16, b, lns, lnb, (unsigned*)h0, (unsigned*)act, n);
    }

    // Layer 0 aggregation + residual(fp16) + LN1 + ReLU.  PDL MODE 1.
    const int spmm_blocks = (n + 7) / 8;
    cfg.gridDim = dim3(spmm_blocks);
    cudaLaunchKernelEx(&cfg, spmm_csr_kernel<true, 1>,
                       (const int*)off, (const int2*)srcw, (const uint2*)act,
                       (const uint2*)h0, (const float*)(lns + HID),
                       (const float*)(lnb + HID), act2, (float4*)nullptr, n);

    // Layer 1 aggregation -> final fp32 output.  PDL MODE 2.
    cudaLaunchKernelEx(&cfg, spmm_csr_kernel<false, 2>,
                       (const int*)off, (const int2*)srcw, (const uint2*)act2,
                       (const uint2*)nullptr, (const float*)nullptr,
                       (const float*)nullptr, (uint2*)nullptr, out, n);
}

// round 17
// speedup vs baseline: 1.7536x; 1.0132x over previous
#include <cuda_runtime.h>
#include <cuda_fp16.h>
#include <cstdint>

#define NMAX 100000
#define EMAX 1600000
#define HID 128
#define EPS 1e-5f
#define CHUNK 1024
#define NBLK ((NMAX + CHUNK - 1) / CHUNK)   // 98
#define GLDA 136    // smem row stride in halfs: 272B = 17 x 16B -> ldmatrix conflict-free

#define FLAG_PART 0x40000000u
#define FLAG_DONE 0x80000000u
#define VAL_MASK  0x3FFFFFFFu

// Scratch (no cudaMalloc allowed).
__device__ uint2  g_h0  [(size_t)NMAX * HID / 4];  // post-linear ("ori"), fp16
__device__ uint2  g_act [(size_t)NMAX * HID / 4];  // layer-0 input, fp16
__device__ uint2  g_act2[(size_t)NMAX * HID / 4];  // layer-1 input, fp16
__device__ half   g_w16 [HID * HID];               // W converted to fp16 (once)
__device__ int2   g_srcw[EMAX];                    // CSR payload: (src, w-bits)
__device__ int    g_rank[EMAX];                    // per-edge rank within dst bucket
__device__ int    g_off [NMAX + 1];
__device__ int    g_deg [NMAX + NBLK];             // deg + lookback state (one memset)

__device__ __forceinline__ unsigned pack_h2(float a, float b)
{
    half2 h = __floats2half2_rn(a, b);
    return *(unsigned*)&h;
}

__device__ __forceinline__ uint2 pack_h4(float a, float b, float c, float d)
{
    return make_uint2(pack_h2(a, b), pack_h2(c, d));
}

__device__ __forceinline__ uint32_t s2u(const void* p)
{
    uint32_t a;
    asm("{ .reg .u64 t; cvta.to.shared.u64 t, %1; cvt.u32.u64 %0, t; }"
        : "=r"(a) : "l"(p));
    return a;
}

__device__ __forceinline__ void ldm_x4(uint32_t* r, uint32_t addr)
{
    asm volatile("ldmatrix.sync.aligned.m8n8.x4.shared.b16 {%0,%1,%2,%3}, [%4];"
                 : "=r"(r[0]), "=r"(r[1]), "=r"(r[2]), "=r"(r[3]) : "r"(addr));
}

__device__ __forceinline__ void mma16816(float* c, const uint32_t* a, const uint32_t* b)
{
    asm volatile("mma.sync.aligned.m16n8k16.row.col.f32.f16.f16.f32 "
                 "{%0,%1,%2,%3}, {%4,%5,%6,%7}, {%8,%9}, {%0,%1,%2,%3};"
                 : "+f"(c[0]), "+f"(c[1]), "+f"(c[2]), "+f"(c[3])
                 : "r"(a[0]), "r"(a[1]), "r"(a[2]), "r"(a[3]),
                   "r"(b[0]), "r"(b[1]));
}

// ---------------------------------------------------------------------------
// One-shot W fp32 -> fp16 conversion (16 blocks x 256; ~2us, on fork stream).
// ---------------------------------------------------------------------------
__global__ void wcvt_kernel(const float* __restrict__ W, half* __restrict__ W16)
{
    int i = blockIdx.x * 256 + threadIdx.x;       // 4096 threads x float4
    float4 w = __ldg((const float4*)&W[i * 4]);
    *(uint2*)&W16[i * 4] = make_uint2(pack_h2(w.x, w.y), pack_h2(w.z, w.w));
}

// ---------------------------------------------------------------------------
// Tensor-core GEMM (fp16 in, fp32 accum) + bias + fused LN0 + ReLU epilogue.
// 512 threads / 16 warps; block tile 128x128; warp tile 16 rows x 64 cols.
// ---------------------------------------------------------------------------
extern __shared__ char smem_raw[];
__global__ void __launch_bounds__(512)
gemm_ln_kernel(const float* __restrict__ x,
               const half* __restrict__ W16,
               const float* __restrict__ b,
               const float* __restrict__ lns,
               const float* __restrict__ lnb,
               unsigned* __restrict__ h0,    // fp16 x2 per word
               unsigned* __restrict__ act,   // fp16 x2 per word
               int n)
{
    half* ws = (half*)smem_raw;               // [128][GLDA] fp16 W
    half* xs = ws + 128 * GLDA;               // [128][GLDA] fp16 x tile
    const int tid  = threadIdx.x;
    const int lane = tid & 31;
    const int warp = tid >> 5;                // 0..15
    const int wr   = warp >> 1;               // row group 0..7
    const int cg   = warp & 1;                // col group 0..1
    const int row0 = blockIdx.x * 128;

    // Stage W: 2048 uint4 (16B) copies
    const uint4* w16v = (const uint4*)W16;
    #pragma unroll
    for (int idx = tid; idx < 2048; idx += 512) {
        int j = idx >> 4, k16 = idx & 15;
        *(uint4*)&ws[j * GLDA + k16 * 8] = __ldg(&w16v[idx]);
    }
    // Stage x: 4096 float4 reads -> uint2 (8B) stores
    #pragma unroll
    for (int idx = tid; idx < 4096; idx += 512) {
        int r = idx >> 5, k4 = idx & 31;
        int row = row0 + r;
        uint2 p = make_uint2(0u, 0u);
        if (row < n) {
            float4 v = __ldg((const float4*)&x[(size_t)row * HID + k4 * 4]);
            p = make_uint2(pack_h2(v.x, v.y), pack_h2(v.z, v.w));
        }
        *(uint2*)&xs[r * GLDA + k4 * 4] = p;
    }
    __syncthreads();

    const uint32_t xs_u = s2u(xs);
    const uint32_t ws_u = s2u(ws);

    float c[8][4];
    #pragma unroll
    for (int t = 0; t < 8; t++)
        #pragma unroll
        for (int i = 0; i < 4; i++) c[t][i] = 0.f;

    const uint32_t a_base = xs_u +
        (uint32_t)(((wr * 16 + (lane & 15)) * GLDA + ((lane >> 4) << 3)) * 2);
    const uint32_t b_base = ws_u +
        (uint32_t)(((cg * 64 + ((lane >> 4) << 3) + (lane & 7)) * GLDA +
                    (((lane >> 3) & 1) << 3)) * 2);

    #pragma unroll
    for (int ks = 0; ks < 8; ks++) {
        const uint32_t koff = ks * 16 * 2;    // bytes
        uint32_t a[4];
        ldm_x4(a, a_base + koff);
        uint32_t bf[4][4];
        #pragma unroll
        for (int tp = 0; tp < 4; tp++)
            ldm_x4(bf[tp], b_base + (uint32_t)(tp * 16 * GLDA * 2) + koff);
        #pragma unroll
        for (int tp = 0; tp < 4; tp++) {
            mma16816(c[2 * tp + 0], a, &bf[tp][0]);
            mma16816(c[2 * tp + 1], a, &bf[tp][2]);
        }
    }

    #pragma unroll
    for (int t = 0; t < 8; t++) {
        float2 bb = __ldg((const float2*)&b[cg * 64 + t * 8 + (lane & 3) * 2]);
        c[t][0] += bb.x; c[t][1] += bb.y;
        c[t][2] += bb.x; c[t][3] += bb.y;
    }

    // Row moments over this warp's 64 cols
    float s_lo = 0.f, s_hi = 0.f, q_lo = 0.f, q_hi = 0.f;
    #pragma unroll
    for (int t = 0; t < 8; t++) {
        s_lo += c[t][0] + c[t][1];
        s_hi += c[t][2] + c[t][3];
        q_lo += c[t][0] * c[t][0] + c[t][1] * c[t][1];
        q_hi += c[t][2] * c[t][2] + c[t][3] * c[t][3];
    }
    #pragma unroll
    for (int o = 1; o <= 2; o <<= 1) {
        s_lo += __shfl_xor_sync(0xffffffffu, s_lo, o);
        s_hi += __shfl_xor_sync(0xffffffffu, s_hi, o);
        q_lo += __shfl_xor_sync(0xffffffffu, q_lo, o);
        q_hi += __shfl_xor_sync(0xffffffffu, q_hi, o);
    }

    float2* red = (float2*)smem_raw;          // [128][2], reuse staging smem
    __syncthreads();
    const int lrow_lo = wr * 16 + (lane >> 2);
    if ((lane & 3) == 0) {
        red[lrow_lo * 2 + cg]       = make_float2(s_lo, q_lo);
        red[(lrow_lo + 8) * 2 + cg] = make_float2(s_hi, q_hi);
    }
    __syncthreads();
    float2 m0 = red[lrow_lo * 2 + 0],       m1 = red[lrow_lo * 2 + 1];
    float2 n0 = red[(lrow_lo + 8) * 2 + 0], n1 = red[(lrow_lo + 8) * 2 + 1];
    const float mu_lo   = (m0.x + m1.x) * (1.f / HID);
    const float mu_hi   = (n0.x + n1.x) * (1.f / HID);
    const float rstd_lo = rsqrtf(fmaxf((m0.y + m1.y) * (1.f / HID) - mu_lo * mu_lo, 0.f) + EPS);
    const float rstd_hi = rsqrtf(fmaxf((n0.y + n1.y) * (1.f / HID) - mu_hi * mu_hi, 0.f) + EPS);

    const int row_lo = row0 + lrow_lo;
    const int row_hi = row_lo + 8;
    const bool v_lo = (row_lo < n), v_hi = (row_hi < n);
    #pragma unroll
    for (int t = 0; t < 8; t++) {
        const int colp = cg * 64 + t * 8 + (lane & 3) * 2;
        float2 sc = __ldg((const float2*)&lns[colp]);
        float2 bi = __ldg((const float2*)&lnb[colp]);
        if (v_lo) {
            h0[(size_t)row_lo * 64 + (colp >> 1)] = pack_h2(c[t][0], c[t][1]);
            act[(size_t)row_lo * 64 + (colp >> 1)] = pack_h2(
                fmaxf((c[t][0] - mu_lo) * rstd_lo * sc.x + bi.x, 0.f),
                fmaxf((c[t][1] - mu_lo) * rstd_lo * sc.y + bi.y, 0.f));
        }
        if (v_hi) {
            h0[(size_t)row_hi * 64 + (colp >> 1)] = pack_h2(c[t][2], c[t][3]);
            act[(size_t)row_hi * 64 + (colp >> 1)] = pack_h2(
                fmaxf((c[t][2] - mu_hi) * rstd_hi * sc.x + bi.x, 0.f),
                fmaxf((c[t][3] - mu_hi) * rstd_hi * sc.y + bi.y, 0.f));
        }
    }
}

// ---------------------------------------------------------------------------
// CSR build.  hist: counts AND captures each edge's rank within its bucket
// (the atomic return value we previously discarded) -> fill needs no atomics.
// ---------------------------------------------------------------------------
__global__ void hist_kernel(const int* __restrict__ dst, int* __restrict__ deg,
                            int* __restrict__ rank, int E)
{
    int e0 = (blockIdx.x * blockDim.x + threadIdx.x) * 4;
    if (e0 + 3 < E) {
        int4 d = *(const int4*)&dst[e0];
        cudaGridDependencySynchronize();
        int4 r;
        r.x = atomicAdd(&deg[d.x], 1);
        r.y = atomicAdd(&deg[d.y], 1);
        r.z = atomicAdd(&deg[d.z], 1);
        r.w = atomicAdd(&deg[d.w], 1);
        *(int4*)&rank[e0] = r;
    } else {
        cudaGridDependencySynchronize();
        for (int e = e0; e < E; e++) rank[e] = atomicAdd(&deg[dst[e]], 1);
    }
}

// Single-pass exclusive scan of deg -> off via decoupled lookback.
__global__ void scan_kernel(const int* __restrict__ deg,
                            unsigned* __restrict__ state,
                            int* __restrict__ off, int n, int nb)
{
    cudaGridDependencySynchronize();          // wait for hist (PDL launch)
    __shared__ int sh[256];
    __shared__ int s_base;
    const int t   = threadIdx.x;
    const int bid = blockIdx.x;
    const int base = bid * CHUNK + t * 4;

    int d[4];
    #pragma unroll
    for (int j = 0; j < 4; j++)
        d[j] = (base + j < n) ? deg[base + j] : 0;
    int local = d[0] + d[1] + d[2] + d[3];

    sh[t] = local;
    __syncthreads();
    for (int o = 1; o < 256; o <<= 1) {       // inclusive Hillis-Steele
        int u = (t >= o) ? sh[t - o] : 0;
        __syncthreads();
        sh[t] += u;
        __syncthreads();
    }

    if (t == 0) {
        unsigned agg = (unsigned)sh[255];
        int run = 0;
        if (bid == 0) {
            atomicExch(&state[0], agg | FLAG_DONE);
        } else {
            atomicExch(&state[bid], agg | FLAG_PART);
            int p = bid - 1;
            for (;;) {
                unsigned s;
                do { s = atomicAdd(&state[p], 0u); } while (s == 0u);
                run += (int)(s & VAL_MASK);
                if (s & FLAG_DONE) break;
                p--;
            }
            atomicExch(&state[bid], ((unsigned)run + agg) | FLAG_DONE);
        }
        s_base = run;
        if (bid == nb - 1) off[n] = run + (int)agg;
    }
    __syncthreads();

    int run = s_base + sh[t] - local;         // exclusive base for elem 0
    #pragma unroll
    for (int j = 0; j < 4; j++) {
        int i = base + j;
        if (i < n) { off[i] = run; run += d[j]; }
    }
}

// fill: atomic-free scatter — slot = off[dst] + rank (captured by hist).
__global__ void fill_kernel(const int* __restrict__ src, const int* __restrict__ dst,
                            const float* __restrict__ ef,
                            const int* __restrict__ off,
                            const int* __restrict__ rank,
                            int2* __restrict__ srcw, int E)
{
    int e0 = (blockIdx.x * blockDim.x + threadIdx.x) * 4;
    if (e0 + 3 < E) {
        int4   s = *(const int4*)&src[e0];
        int4   d = *(const int4*)&dst[e0];
        float4 w = *(const float4*)&ef[e0];
        int4   r = *(const int4*)&rank[e0];
        cudaGridDependencySynchronize();       // wait scan (off ready)
        srcw[__ldg(&off[d.x]) + r.x] = make_int2(s.x, __float_as_int(w.x));
        srcw[__ldg(&off[d.y]) + r.y] = make_int2(s.y, __float_as_int(w.y));
        srcw[__ldg(&off[d.z]) + r.z] = make_int2(s.z, __float_as_int(w.z));
        srcw[__ldg(&off[d.w]) + r.w] = make_int2(s.w, __float_as_int(w.w));
    } else {
        cudaGridDependencySynchronize();
        for (int e = e0; e < E; e++)
            srcw[__ldg(&off[dst[e]]) + rank[e]] =
                make_int2(src[e], __float_as_int(ef[e]));
    }
}

// ---------------------------------------------------------------------------
// SpMM gather-reduce over fp16 features, fp32 accumulation.
// MODE 0: plain.  MODE 1: PDL, prefetch off only.  MODE 2: PDL, prefetch
// off + first srcw batch.
// ---------------------------------------------------------------------------
template <bool FUSE_LN, int MODE>
__global__ void spmm_csr_kernel(const int* __restrict__ off,
                                const int2* __restrict__ srcw,
                                const uint2* __restrict__ hin,
                                const uint2* __restrict__ h16,
                                const float* __restrict__ lns,
                                const float* __restrict__ lnb,
                                uint2* __restrict__ out_h,
                                float4* __restrict__ out_f, int n)
{
    const int node = blockIdx.x * 8 + (threadIdx.x >> 5);
    const int lane = threadIdx.x & 31;
    if (node >= n) {
        if (MODE != 0) cudaGridDependencySynchronize();
        return;
    }

    const int beg = off[node];
    const int end = off[node + 1];

    int cnt = min(end - beg, 32);
    int2 sw = make_int2(0, 0);
    if (MODE == 2) {
        if (lane < cnt) sw = __ldg(&srcw[beg + lane]);
    }
    if (MODE != 0) cudaGridDependencySynchronize();
    if (MODE != 2) {
        if (lane < cnt) sw = __ldg(&srcw[beg + lane]);
    }

    float4 a = make_float4(0.f, 0.f, 0.f, 0.f);
    for (int base = beg; base < end; base += 32) {
        #pragma unroll 8
        for (int j = 0; j < cnt; j++) {
            int   s = __shfl_sync(0xffffffffu, sw.x, j);
            float w = __int_as_float(__shfl_sync(0xffffffffu, sw.y, j));
            uint2 p = __ldg(&hin[(size_t)s * 32 + lane]);
            float2 lo = __half22float2(*(half2*)&p.x);
            float2 hi = __half22float2(*(half2*)&p.y);
            a.x += lo.x * w; a.y += lo.y * w;
            a.z += hi.x * w; a.w += hi.y * w;
        }
        int nb2 = base + 32;
        if (nb2 < end) {
            cnt = min(end - nb2, 32);
            sw = make_int2(0, 0);
            if (lane < cnt) sw = __ldg(&srcw[nb2 + lane]);
        }
    }

    if (FUSE_LN) {
        uint2 rp = __ldg(&h16[(size_t)node * 32 + lane]);
        float2 rlo = __half22float2(*(half2*)&rp.x);
        float2 rhi = __half22float2(*(half2*)&rp.y);
        a.x += rlo.x; a.y += rlo.y; a.z += rhi.x; a.w += rhi.y;

        float s = a.x + a.y + a.z + a.w;
        #pragma unroll
        for (int o = 16; o > 0; o >>= 1) s += __shfl_xor_sync(0xffffffffu, s, o);
        float mu = s * (1.f / HID);
        float dx = a.x - mu, dy = a.y - mu, dz = a.z - mu, dw = a.w - mu;
        float q = dx * dx + dy * dy + dz * dz + dw * dw;
        #pragma unroll
        for (int o = 16; o > 0; o >>= 1) q += __shfl_xor_sync(0xffffffffu, q, o);
        float rstd = rsqrtf(q * (1.f / HID) + EPS);

        int j0 = lane * 4;
        float4 sc = __ldg((const float4*)&lns[j0]);
        float4 bi = __ldg((const float4*)&lnb[j0]);
        out_h[(size_t)node * 32 + lane] = pack_h4(
            fmaxf(dx * rstd * sc.x + bi.x, 0.f),
            fmaxf(dy * rstd * sc.y + bi.y, 0.f),
            fmaxf(dz * rstd * sc.z + bi.z, 0.f),
            fmaxf(dw * rstd * sc.w + bi.w, 0.f));
    } else {
        out_f[(size_t)node * 32 + lane] = a;
    }
}

// ---------------------------------------------------------------------------
extern "C" void kernel_launch(void* const* d_in, const int* in_sizes, int n_in,
                              void* d_out, int out_size)
{
    const float* x   = (const float*)d_in[0];
    const int*   ei  = (const int*)d_in[1];     // [2, E] int32
    const float* ef  = (const float*)d_in[2];
    const float* W   = (const float*)d_in[3];
    const float* b   = (const float*)d_in[4];
    const float* lns = (const float*)d_in[5];
    const float* lnb = (const float*)d_in[6];

    const int n = in_sizes[0] / HID;
    const int E = in_sizes[2];
    float4* out = (float4*)d_out;

    uint2 *h0, *act, *act2; half* w16; int2* srcw; int *rank, *off, *deg;
    cudaGetSymbolAddress((void**)&h0,   g_h0);
    cudaGetSymbolAddress((void**)&act,  g_act);
    cudaGetSymbolAddress((void**)&act2, g_act2);
    cudaGetSymbolAddress((void**)&w16,  g_w16);
    cudaGetSymbolAddress((void**)&srcw, g_srcw);
    cudaGetSymbolAddress((void**)&rank, g_rank);
    cudaGetSymbolAddress((void**)&off,  g_off);
    cudaGetSymbolAddress((void**)&deg,  g_deg);
    unsigned* state = (unsigned*)(deg + NMAX);

    const int nb = (n + CHUNK - 1) / CHUNK;

    // Fork resources (host-side only; created per call, never destroyed —
    // kernel_launch runs a handful of times, destroying mid-capture is illegal).
    cudaStream_t s2 = 0;
    cudaEvent_t evFork = 0, evJoin = 0;
    bool forked =
        (cudaStreamCreateWithFlags(&s2, cudaStreamNonBlocking) == cudaSuccess) &&
        (cudaEventCreateWithFlags(&evFork, cudaEventDisableTiming) == cudaSuccess) &&
        (cudaEventCreateWithFlags(&evJoin, cudaEventDisableTiming) == cudaSuccess);

    cudaLaunchAttribute pa[1];
    pa[0].id = cudaLaunchAttributeProgrammaticStreamSerialization;
    pa[0].val.programmaticStreamSerializationAllowed = 1;

    cudaLaunchConfig_t cfg{};
    cfg.blockDim = dim3(256);
    cfg.dynamicSmemBytes = 0;
    cfg.stream = 0;
    cfg.attrs = pa;
    cfg.numAttrs = 1;

    // Fork: wcvt + gemm on s2, concurrent with the CSR chain on stream 0.
    const int gemm_blocks = (n + 127) / 128;
    const int gemm_smem = 2 * 128 * GLDA * (int)sizeof(half);   // 69632 B
    cudaFuncSetAttribute(gemm_ln_kernel,
                         cudaFuncAttributeMaxDynamicSharedMemorySize, gemm_smem);
    if (forked) {
        cudaEventRecord(evFork, 0);
        cudaStreamWaitEvent(s2, evFork, 0);
        wcvt_kernel<<<16, 256, 0, s2>>>(W, w16);
        gemm_ln_kernel<<<gemm_blocks, 512, gemm_smem, s2>>>(
            x, w16, b, lns, lnb, (unsigned*)h0, (unsigned*)act, n);
        cudaEventRecord(evJoin, s2);
    }

    // Stream 0: CSR build chain (PDL within the chain).
    cudaMemsetAsync(deg, 0, (size_t)(NMAX + NBLK) * sizeof(int), 0);

    cfg.gridDim = dim3((E / 4 + 255) / 256);
    cudaLaunchKernelEx(&cfg, hist_kernel, ei + E, deg, rank, E);

    cfg.gridDim = dim3(nb);
    cudaLaunchKernelEx(&cfg, scan_kernel, (const int*)deg, state, off, n, nb);

    cfg.gridDim = dim3((E / 4 + 255) / 256);
    cudaLaunchKernelEx(&cfg, fill_kernel, ei, ei + E, ef,
                       (const int*)off, (const int*)rank, srcw, E);

    if (forked) {
        cudaStreamWaitEvent(0, evJoin, 0);    // join gemm before spmm0
    } else {
        wcvt_kernel<<<16, 256>>>(W, w16);
        gemm_ln_kernel<<<gemm_blocks, 512, gemm_smem, 0>>>(
            x, w16, b, lns, lnb, (unsigned*)h0, (unsigned*)act, n);
    }

    // Layer 0 aggregation + residual(fp16) + LN1 + ReLU.  PDL MODE 1.
    const int spmm_blocks = (n + 7) / 8;
    cfg.gridDim = dim3(spmm_blocks);
    cudaLaunchKernelEx(&cfg, spmm_csr_kernel<true, 1>,
                       (const int*)off, (const int2*)srcw, (const uint2*)act,
                       (const uint2*)h0, (const float*)(lns + HID),
                       (const float*)(lnb + HID), act2, (float4*)nullptr, n);

    // Layer 1 aggregation -> final fp32 output.  PDL MODE 2.
    cudaLaunchKernelEx(&cfg, spmm_csr_kernel<false, 2>,
                       (const int*)off, (const int2*)srcw, (const uint2*)act2,
                       (const uint2*)nullptr, (const float*)nullptr,
                       (const float*)nullptr, (uint2*)nullptr, out, n);
}